// round 10
// baseline (speedup 1.0000x reference)
#include <cuda_runtime.h>
#include <math.h>

#define PI_F 3.14159265358979323846f
#define N_NODES 4096
#define N_EDGES 12288
#define NUM_GRAPHS 16
#define PQC_BLOCKS 1024

// ---------------- device scratch ----------------
__device__ float  g_x[N_NODES * 2];
__device__ float4 g_x4[N_NODES];
__device__ float4 g_e4[N_EDGES];
// [0..3] (c,s) CRX,CRY1,CRZ,CRY2 ; [4..7] Re [8..11] Rnb [12..15] Ra1
// [16..19] Ra1p [20..23] Rnbp [24..27] Ra2 ; [28..31] Q3=H*U0 [32..35] Q1=H*U1
__device__ float2 g_gates[36];
__device__ float2 g_w[64];
__device__ float  g_gsum[NUM_GRAPHS * 2];
__device__ float  g_gcnt[NUM_GRAPHS];
__device__ int    g_done;
__device__ int    g_bar;

// ---------------- complex helpers ----------------
__device__ __forceinline__ float2 cmul(float2 a, float2 b) {
    return make_float2(fmaf(a.x, b.x, -(a.y * b.y)), fmaf(a.x, b.y, a.y * b.x));
}
__device__ __forceinline__ float2 cfma(float2 a, float2 b, float2 c) {
    return make_float2(fmaf(a.x, b.x, fmaf(-a.y, b.y, c.x)),
                       fmaf(a.x, b.y, fmaf( a.y, b.x, c.y)));
}
__device__ __forceinline__ float2 cadd(float2 a, float2 b) {
    return make_float2(a.x + b.x, a.y + b.y);
}

// ================= PQC register-gate primitives =================
template <int J>
__device__ __forceinline__ void ap_reg(float2* v, const float2* U) {
    float2 u0 = U[0], u1 = U[1], u2 = U[2], u3 = U[3];
#pragma unroll
    for (int r = 0; r < 16; r++) {
        if ((r >> J) & 1) continue;
        int r2 = r | (1 << J);
        float2 a = v[r], b = v[r2];
        v[r]  = cfma(u1, b, cmul(u0, a));
        v[r2] = cfma(u3, b, cmul(u2, a));
    }
}
template <int C, int T>
__device__ __forceinline__ void crx_rr(float2* v, float c, float s) {
#pragma unroll
    for (int r = 0; r < 16; r++) {
        if (!((r >> C) & 1) || ((r >> T) & 1)) continue;
        int r2 = r | (1 << T);
        float2 a = v[r], b = v[r2];
        v[r]  = make_float2(fmaf(c, a.x,  s * b.y), fmaf(c, a.y, -s * b.x));
        v[r2] = make_float2(fmaf(c, b.x,  s * a.y), fmaf(c, b.y, -s * a.x));
    }
}
template <int C, int T>
__device__ __forceinline__ void cry_rr(float2* v, float c, float s) {
#pragma unroll
    for (int r = 0; r < 16; r++) {
        if (!((r >> C) & 1) || ((r >> T) & 1)) continue;
        int r2 = r | (1 << T);
        float2 a = v[r], b = v[r2];
        v[r]  = make_float2(fmaf(c, a.x, -s * b.x), fmaf(c, a.y, -s * b.y));
        v[r2] = make_float2(fmaf(c, b.x,  s * a.x), fmaf(c, b.y,  s * a.y));
    }
}
template <int C, int T>
__device__ __forceinline__ void crz_rr(float2* v, float c, float s) {
#pragma unroll
    for (int r = 0; r < 16; r++) {
        if (!((r >> C) & 1)) continue;
        float sg = ((r >> T) & 1) ? -s : s;
        float2 a = v[r];
        v[r] = make_float2(fmaf(c, a.x, sg * a.y), fmaf(c, a.y, -sg * a.x));
    }
}
template <int C, int T>
__device__ __forceinline__ void cnot_rr(float2* v) {
#pragma unroll
    for (int r = 0; r < 16; r++) {
        if (!((r >> C) & 1) || ((r >> T) & 1)) continue;
        int r2 = r | (1 << T);
        float2 t = v[r]; v[r] = v[r2]; v[r2] = t;
    }
}
template <int J>
__device__ __forceinline__ void swap_reg_lane(float2* v, int lane, int mask) {
    bool b = lane & mask;
#pragma unroll
    for (int r = 0; r < 16; r++) {
        if ((r >> J) & 1) continue;
        int r2 = r | (1 << J);
        float2 send = b ? v[r] : v[r2];
        float2 recv;
        recv.x = __shfl_xor_sync(0xffffffffu, send.x, mask);
        recv.y = __shfl_xor_sync(0xffffffffu, send.y, mask);
        if (b) v[r] = recv; else v[r2] = recv;
    }
}

__device__ __forceinline__ void iter_regs(float2* v, const float2* sG) {
    crx_rr<2, 1>(v, sG[0].x, sG[0].y);
    cry_rr<3, 1>(v, sG[1].x, sG[1].y);
    crz_rr<2, 0>(v, sG[2].x, sG[2].y);
    cry_rr<3, 0>(v, sG[3].x, sG[3].y);
    ap_reg<3>(v, sG + 4);
    ap_reg<2>(v, sG + 8);
    ap_reg<1>(v, sG + 12);
    cnot_rr<3, 2>(v);
    cnot_rr<2, 1>(v);
    cnot_rr<1, 3>(v);
    ap_reg<1>(v, sG + 16);
    ap_reg<2>(v, sG + 20);
    ap_reg<0>(v, sG + 24);
    cnot_rr<1, 2>(v);
    cnot_rr<2, 0>(v);
    cnot_rr<0, 1>(v);
}

// ---------------- gate precompute ----------------
__device__ void make_rot(const float* w, float2* m) {
    float phi = w[0], th = w[1], om = w[2];
    float c, s; sincosf(th * 0.5f, &s, &c);
    float sa, ca, sb, cb;
    sincosf((phi + om) * 0.5f, &sa, &ca);
    sincosf((phi - om) * 0.5f, &sb, &cb);
    m[0] = make_float2(c * ca, -c * sa);
    m[1] = make_float2(-s * cb, -s * sb);
    m[2] = make_float2(s * cb, -s * sb);
    m[3] = make_float2(c * ca, c * sa);
}
__device__ void cm2(const float2* A, const float2* B, float2* C) {
    C[0] = cadd(cmul(A[0], B[0]), cmul(A[1], B[2]));
    C[1] = cadd(cmul(A[0], B[1]), cmul(A[1], B[3]));
    C[2] = cadd(cmul(A[2], B[0]), cmul(A[3], B[2]));
    C[3] = cadd(cmul(A[2], B[1]), cmul(A[3], B[3]));
}
__device__ void prep_gates(const float* strong, const float* inits, const float* update) {
    float c, s;
    sincosf(inits[0] * 0.5f, &s, &c); g_gates[0] = make_float2(c, s);
    sincosf(inits[1] * 0.5f, &s, &c); g_gates[1] = make_float2(c, s);
    sincosf(inits[2] * 0.5f, &s, &c); g_gates[2] = make_float2(c, s);
    sincosf(inits[3] * 0.5f, &s, &c); g_gates[3] = make_float2(c, s);
    float2 M[4], Q[4];
    make_rot(strong + 0,  M); for (int k = 0; k < 4; k++) g_gates[4 + k]  = M[k];
    make_rot(strong + 3,  M); for (int k = 0; k < 4; k++) g_gates[8 + k]  = M[k];
    make_rot(strong + 6,  M); for (int k = 0; k < 4; k++) g_gates[12 + k] = M[k];
    make_rot(strong + 9,  M); for (int k = 0; k < 4; k++) g_gates[16 + k] = M[k];
    make_rot(strong + 12, M); for (int k = 0; k < 4; k++) g_gates[20 + k] = M[k];
    make_rot(strong + 15, M); for (int k = 0; k < 4; k++) g_gates[24 + k] = M[k];
    const float rh = 0.70710678118654752f;
    float2 H2[4];
    H2[0] = make_float2(rh, 0); H2[1] = make_float2(rh, 0);
    H2[2] = make_float2(rh, 0); H2[3] = make_float2(-rh, 0);
    make_rot(update + 0, M); cm2(H2, M, Q); for (int k = 0; k < 4; k++) g_gates[28 + k] = Q[k];
    make_rot(update + 3, M); cm2(H2, M, Q); for (int k = 0; k < 4; k++) g_gates[32 + k] = Q[k];
}

__device__ __forceinline__ float2 pick(float4 a, int bit) {
    return bit ? make_float2(a.z, a.w) : make_float2(a.x, a.y);
}

// ---------------- phase-1 MLP: 8 threads per row, 16 rows per block ----------------
template <int NI, bool IS_NODE>
__device__ __forceinline__ void mlp_phase(const float* __restrict__ inp, int row, int k8,
                                          const float* sMW1, const float* sMb1,
                                          const float* sMW2, const float* sMb2) {
    float in[NI];
#pragma unroll
    for (int i = 0; i < NI; i++) in[i] = inp[row * NI + i];
    float o0 = 0.f, o1 = 0.f;
#pragma unroll
    for (int j = 0; j < 16; j++) {
        int h = k8 + 8 * j;
        float a = sMb1[h];
#pragma unroll
        for (int i = 0; i < NI; i++) a = fmaf(in[i], sMW1[i * 128 + h], a);
        a = a > 0.f ? a : 0.01f * a;
        o0 = fmaf(a, sMW2[2 * h], o0);
        o1 = fmaf(a, sMW2[2 * h + 1], o1);
    }
#pragma unroll
    for (int o = 1; o < 8; o <<= 1) {
        o0 += __shfl_xor_sync(0xffffffffu, o0, o);
        o1 += __shfl_xor_sync(0xffffffffu, o1, o);
    }
    if (k8 == 0) {
        o0 += sMb2[0]; o1 += sMb2[1];
        float t0 = tanhf(o0) * PI_F;
        float t1 = tanhf(o1) * PI_F;
        float sy, cy, sz, cz;
        sincosf(0.5f * t0, &sy, &cy);
        sincosf(0.5f * t1, &sz, &cz);
        float4 amps = make_float4(cy * cz, -cy * sz, sy * cz, sy * sz);
        if (IS_NODE) {
            g_x[2 * row] = t0; g_x[2 * row + 1] = t1;
            g_x4[row] = amps;
        } else {
            g_e4[row] = amps;
        }
    }
}

// ================= fused single kernel =================
__global__ void __launch_bounds__(128, 8) qgnn_kernel(
    const float* __restrict__ node_feat,
    const float* __restrict__ Wn1, const float* __restrict__ bn1,
    const float* __restrict__ Wn2, const float* __restrict__ bn2,
    const float* __restrict__ edge_attr,
    const float* __restrict__ We1, const float* __restrict__ be1,
    const float* __restrict__ We2, const float* __restrict__ be2,
    const float* __restrict__ strong, const float* __restrict__ inits,
    const float* __restrict__ update,
    const int* __restrict__ subgraphs, const int* __restrict__ edge_ids,
    const int* __restrict__ batch,
    const float* __restrict__ Wu1, const float* __restrict__ bu1,
    const float* __restrict__ Wu2, const float* __restrict__ bu2,
    const float* __restrict__ Wh1, const float* __restrict__ bh1,
    const float* __restrict__ Wh2, const float* __restrict__ bh2,
    float* __restrict__ out) {
    __shared__ float sMW1[8 * 128];
    __shared__ float sMb1[128];
    __shared__ float sMW2[256];
    __shared__ float sMb2[2];
    __shared__ float2 sG[36];
    __shared__ float2 sWC[64];
    __shared__ float sW1[384];
    __shared__ float sb1[128];
    __shared__ float sW2[256];
    __shared__ float sb2[2];
    __shared__ float sAcc[NUM_GRAPHS * 3];
    __shared__ int sLast;
    int b = blockIdx.x, tid = threadIdx.x;

    // ======== phase 1: node/edge MLP ========
    bool isNode = (b < 256);
    {
        const float* W1 = isNode ? Wn1 : We1;
        const float* b1 = isNode ? bn1 : be1;
        const float* W2 = isNode ? Wn2 : We2;
        const float* b2 = isNode ? bn2 : be2;
        int ni = isNode ? 8 : 4;
        for (int k = tid; k < ni * 128; k += 128) sMW1[k] = W1[k];
        sMb1[tid] = b1[tid];
        sMW2[tid] = W2[tid]; sMW2[128 + tid] = W2[128 + tid];
        if (tid < 2) sMb2[tid] = b2[tid];
    }
    // preload upd weights (independent of phase 1)
    for (int k = tid; k < 384; k += 128) sW1[k] = Wu1[k];
    sb1[tid] = bu1[tid];
    sW2[tid] = Wu2[tid]; sW2[128 + tid] = Wu2[128 + tid];
    if (tid < 2) sb2[tid] = bu2[tid];
    if (tid < NUM_GRAPHS * 3) sAcc[tid] = 0.f;
    __syncthreads();

    int k8 = tid & 7;
    if (isNode)
        mlp_phase<8, true>(node_feat, b * 16 + (tid >> 3), k8, sMW1, sMb1, sMW2, sMb2);
    else
        mlp_phase<4, false>(edge_attr, (b - 256) * 16 + (tid >> 3), k8, sMW1, sMb1, sMW2, sMb2);

    // block 0: prep gates, zero accumulators, compute W columns
    if (b == 0) {
        __syncthreads();
        if (tid < NUM_GRAPHS) {
            g_gsum[2 * tid] = 0.f; g_gsum[2 * tid + 1] = 0.f; g_gcnt[tid] = 0.f;
        }
        if (tid == 32) prep_gates(strong, inits, update);
        __syncthreads();
        if (tid >= 64 && tid < 68) {
            int k = tid - 64;
            float2 v[16];
#pragma unroll
            for (int r = 0; r < 16; r++) v[r] = make_float2(0.f, 0.f);
            v[((k >> 1) << 3) | ((k & 1) << 2)] = make_float2(1.f, 0.f);
            iter_regs(v, g_gates);
#pragma unroll
            for (int r = 0; r < 16; r++) g_w[k * 16 + r] = v[r];
        }
    }

    // ======== grid barrier (all 1024 blocks co-resident by launch_bounds) ========
    __threadfence();
    __syncthreads();
    if (tid == 0) {
        atomicAdd(&g_bar, 1);
        while (*(volatile int*)&g_bar < PQC_BLOCKS) __nanosleep(64);
    }
    __syncthreads();
    __threadfence();

    // ======== phase 2: PQC ========
    if (tid < 36) sG[tid] = g_gates[tid];
    if (tid >= 64) sWC[tid - 64] = g_w[tid - 64];
    __syncthreads();

    int lane = tid & 31;
    int s = b * 4 + (tid >> 5);

    int e0 = edge_ids[3 * s], e1 = edge_ids[3 * s + 1], e2 = edge_ids[3 * s + 2];
    int n0 = subgraphs[4 * s], n1 = subgraphs[4 * s + 1],
        n2 = subgraphs[4 * s + 2], n3 = subgraphs[4 * s + 3];

    float x0c = g_x[2 * n0], x1c = g_x[2 * n0 + 1];

    float2 lf = pick(g_e4[e1], (lane >> 4) & 1);
    lf = cmul(lf, pick(g_e4[e2], (lane >> 3) & 1));
    lf = cmul(lf, pick(g_x4[n0], (lane >> 2) & 1));
    lf = cmul(lf, pick(g_x4[n2], (lane >> 1) & 1));
    lf = cmul(lf, pick(g_x4[n3], lane & 1));
    float4 aw0 = g_e4[e0];
    float4 aw4 = g_x4[n1];

    float2 c0 = cmul(lf, cmul(pick(aw0, 0), pick(aw4, 0)));
    float2 c1 = cmul(lf, cmul(pick(aw0, 0), pick(aw4, 1)));
    float2 c2 = cmul(lf, cmul(pick(aw0, 1), pick(aw4, 0)));
    float2 c3 = cmul(lf, cmul(pick(aw0, 1), pick(aw4, 1)));

    float2 v[16];
#pragma unroll
    for (int r = 0; r < 16; r++)
        v[r] = cfma(c3, sWC[48 + r],
               cfma(c2, sWC[32 + r],
               cfma(c1, sWC[16 + r],
               cmul(c0, sWC[r]))));

    swap_reg_lane<3>(v, lane, 16);
    swap_reg_lane<2>(v, lane, 2);
    iter_regs(v, sG);                     // iteration 1: e=w1, nb=w5
    swap_reg_lane<3>(v, lane, 8);
    swap_reg_lane<2>(v, lane, 1);
    iter_regs(v, sG);                     // iteration 2: e=w2, nb=w6
    swap_reg_lane<3>(v, lane, 4);         // R3 <- w3

    ap_reg<3>(v, sG + 28);
    ap_reg<1>(v, sG + 32);

    float part = 0.f;
#pragma unroll
    for (int r = 0; r < 16; r++) {
        float t = fmaf(v[r].x, v[r].x, v[r].y * v[r].y);
        part = (((r >> 3) ^ (r >> 1)) & 1) ? part - t : part + t;
    }
#pragma unroll
    for (int o = 16; o; o >>= 1) part += __shfl_xor_sync(0xffffffffu, part, o);
    float aggr = part;

    float o0 = 0.f, o1 = 0.f;
#pragma unroll
    for (int k = 0; k < 4; k++) {
        int h = lane + 32 * k;
        float a = fmaf(x0c, sW1[h],
                  fmaf(x1c, sW1[128 + h],
                  fmaf(aggr, sW1[256 + h], sb1[h])));
        a = a > 0.f ? a : 0.01f * a;
        o0 = fmaf(a, sW2[2 * h], o0);
        o1 = fmaf(a, sW2[2 * h + 1], o1);
    }
#pragma unroll
    for (int o = 16; o; o >>= 1) {
        o0 += __shfl_xor_sync(0xffffffffu, o0, o);
        o1 += __shfl_xor_sync(0xffffffffu, o1, o);
    }
    if (lane == 0) {
        o0 += sb2[0]; o1 += sb2[1];
        int gu = batch[n0];
        int gx = batch[s];
        atomicAdd(&sAcc[3 * gu + 0], o0);
        atomicAdd(&sAcc[3 * gu + 1], o1);
        atomicAdd(&sAcc[3 * gx + 0], g_x[2 * s]);
        atomicAdd(&sAcc[3 * gx + 1], g_x[2 * s + 1]);
        atomicAdd(&sAcc[3 * gx + 2], 1.f);
    }
    __syncthreads();

    if (tid < NUM_GRAPHS) {
        atomicAdd(&g_gsum[2 * tid],     sAcc[3 * tid + 0]);
        atomicAdd(&g_gsum[2 * tid + 1], sAcc[3 * tid + 1]);
        atomicAdd(&g_gcnt[tid],         sAcc[3 * tid + 2]);
        __threadfence();
    }
    __syncthreads();
    if (tid == 0) {
        int old = atomicAdd(&g_done, 1);
        sLast = (old == PQC_BLOCKS - 1);
        __threadfence();
    }
    __syncthreads();

    if (sLast) {
        if (tid < NUM_GRAPHS) {
            int g = tid;
            float cnt = __ldcg(&g_gcnt[g]);
            float g0 = __ldcg(&g_gsum[2 * g]) / cnt;
            float g1 = __ldcg(&g_gsum[2 * g + 1]) / cnt;
            float h0 = g0 * Wh1[0] + g1 * Wh1[2] + bh1[0];
            float h1 = g0 * Wh1[1] + g1 * Wh1[3] + bh1[1];
            h0 = h0 > 0.f ? h0 : 0.01f * h0;
            h1 = h1 > 0.f ? h1 : 0.01f * h1;
            out[2 * g]     = h0 * Wh2[0] + h1 * Wh2[2] + bh2[0];
            out[2 * g + 1] = h0 * Wh2[1] + h1 * Wh2[3] + bh2[1];
        }
        // reset barrier/done counters for the next graph replay
        if (tid == 32) { g_bar = 0; g_done = 0; }
    }
}

// ---------------- launch ----------------
extern "C" void kernel_launch(void* const* d_in, const int* in_sizes, int n_in,
                              void* d_out, int out_size) {
    const float* node_feat = (const float*)d_in[0];
    const float* edge_attr = (const float*)d_in[1];
    const float* Wn1 = (const float*)d_in[2];
    const float* bn1 = (const float*)d_in[3];
    const float* Wn2 = (const float*)d_in[4];
    const float* bn2 = (const float*)d_in[5];
    const float* We1 = (const float*)d_in[6];
    const float* be1 = (const float*)d_in[7];
    const float* We2 = (const float*)d_in[8];
    const float* be2 = (const float*)d_in[9];
    const float* strong = (const float*)d_in[10];
    const float* inits  = (const float*)d_in[11];
    const float* update = (const float*)d_in[12];
    const float* Wu1 = (const float*)d_in[13];
    const float* bu1 = (const float*)d_in[14];
    const float* Wu2 = (const float*)d_in[15];
    const float* bu2 = (const float*)d_in[16];
    const float* Wh1 = (const float*)d_in[17];
    const float* bh1 = (const float*)d_in[18];
    const float* Wh2 = (const float*)d_in[19];
    const float* bh2 = (const float*)d_in[20];
    const int* subgraphs = (const int*)d_in[21];
    const int* edge_ids  = (const int*)d_in[22];
    const int* batch     = (const int*)d_in[23];
    float* out = (float*)d_out;

    qgnn_kernel<<<PQC_BLOCKS, 128>>>(node_feat, Wn1, bn1, Wn2, bn2,
                                     edge_attr, We1, be1, We2, be2,
                                     strong, inits, update,
                                     subgraphs, edge_ids, batch,
                                     Wu1, bu1, Wu2, bu2,
                                     Wh1, bh1, Wh2, bh2, out);
}

// round 11
// speedup vs baseline: 1.1313x; 1.1313x over previous
#include <cuda_runtime.h>
#include <math.h>

#define PI_F 3.14159265358979323846f
#define N_NODES 4096
#define N_EDGES 12288
#define NUM_GRAPHS 16
#define PQC_BLOCKS 1024

typedef unsigned long long ull;

// ---------------- device scratch ----------------
__device__ float  g_x[N_NODES * 2];
__device__ float4 g_x4[N_NODES];
__device__ float4 g_e4[N_EDGES];
// scalar gate table: [0..3] (c,s) CRX,CRY1,CRZ,CRY2 ; [4..7] Re [8..11] Rnb
// [12..15] Ra1 [16..19] Ra1p [20..23] Rnbp [24..27] Ra2 [28..31] Q3 [32..35] Q1
__device__ float2 g_gates[36];
// packed gate table (ull splats):
// 0:Re 8:Rnb 16:Ra1 24:Ra1p 32:Rnbp 40:Q3 48:Q1 (8 each: u0x,u0y,nu0y,u1x,nu1x,u1y,nu1y,nu0x)
// 56..61: Ra2 (alpha,beta,gamma,delta,alphap,betap)
// 62..64: crx c,s,ns  65..67: cry01 c,s,ns  68..70: crz c,sp,sn  71..72: crya2 c,sm
__device__ ull    g_gp[73];
__device__ ull    g_wp[64];   // 4 iter0 columns packed: col k: [k*16+p]=re, [k*16+8+p]=im
__device__ float  g_gsum[NUM_GRAPHS * 2];
__device__ float  g_gcnt[NUM_GRAPHS];
__device__ int    g_done;

// ---------------- packed helpers ----------------
__device__ __forceinline__ ull pk(float x, float y) {
    ull r; asm("mov.b64 %0,{%1,%2};" : "=l"(r) : "f"(x), "f"(y)); return r;
}
__device__ __forceinline__ void upk(ull a, float& x, float& y) {
    asm("mov.b64 {%0,%1},%2;" : "=f"(x), "=f"(y) : "l"(a));
}
__device__ __forceinline__ ull fma2(ull a, ull b, ull c) {
    ull r; asm("fma.rn.f32x2 %0,%1,%2,%3;" : "=l"(r) : "l"(a), "l"(b), "l"(c)); return r;
}
__device__ __forceinline__ ull mul2(ull a, ull b) {
    ull r; asm("mul.rn.f32x2 %0,%1,%2;" : "=l"(r) : "l"(a), "l"(b)); return r;
}
__device__ __forceinline__ ull hsw(ull a) {     // swap halves
    float x, y; upk(a, x, y); return pk(y, x);
}
__device__ __forceinline__ void swp(ull& a, ull& b) { ull t = a; a = b; b = t; }
__device__ __forceinline__ void yswp(ull& A, ull& B) {   // swap .y halves
    float ax, ay, bx, by; upk(A, ax, ay); upk(B, bx, by);
    A = pk(ax, by); B = pk(bx, ay);
}

// ---------------- complex (scalar) helpers ----------------
__device__ __forceinline__ float2 cmul(float2 a, float2 b) {
    return make_float2(fmaf(a.x, b.x, -(a.y * b.y)), fmaf(a.x, b.y, a.y * b.x));
}
__device__ __forceinline__ float2 cfma(float2 a, float2 b, float2 c) {
    return make_float2(fmaf(a.x, b.x, fmaf(-a.y, b.y, c.x)),
                       fmaf(a.x, b.y, fmaf( a.y, b.x, c.y)));
}
__device__ __forceinline__ float2 cadd(float2 a, float2 b) {
    return make_float2(a.x + b.x, a.y + b.y);
}

// ================= scalar gate primitives (prep/W-columns only) =================
template <int J>
__device__ void ap_reg_s(float2* v, const float2* U) {
    float2 u0 = U[0], u1 = U[1], u2 = U[2], u3 = U[3];
#pragma unroll
    for (int r = 0; r < 16; r++) {
        if ((r >> J) & 1) continue;
        int r2 = r | (1 << J);
        float2 a = v[r], b = v[r2];
        v[r]  = cfma(u1, b, cmul(u0, a));
        v[r2] = cfma(u3, b, cmul(u2, a));
    }
}
template <int C, int T>
__device__ void crx_s(float2* v, float c, float s) {
#pragma unroll
    for (int r = 0; r < 16; r++) {
        if (!((r >> C) & 1) || ((r >> T) & 1)) continue;
        int r2 = r | (1 << T);
        float2 a = v[r], b = v[r2];
        v[r]  = make_float2(fmaf(c, a.x,  s * b.y), fmaf(c, a.y, -s * b.x));
        v[r2] = make_float2(fmaf(c, b.x,  s * a.y), fmaf(c, b.y, -s * a.x));
    }
}
template <int C, int T>
__device__ void cry_s(float2* v, float c, float s) {
#pragma unroll
    for (int r = 0; r < 16; r++) {
        if (!((r >> C) & 1) || ((r >> T) & 1)) continue;
        int r2 = r | (1 << T);
        float2 a = v[r], b = v[r2];
        v[r]  = make_float2(fmaf(c, a.x, -s * b.x), fmaf(c, a.y, -s * b.y));
        v[r2] = make_float2(fmaf(c, b.x,  s * a.x), fmaf(c, b.y,  s * a.y));
    }
}
template <int C, int T>
__device__ void crz_s(float2* v, float c, float s) {
#pragma unroll
    for (int r = 0; r < 16; r++) {
        if (!((r >> C) & 1)) continue;
        float sg = ((r >> T) & 1) ? -s : s;
        float2 a = v[r];
        v[r] = make_float2(fmaf(c, a.x, sg * a.y), fmaf(c, a.y, -sg * a.x));
    }
}
template <int C, int T>
__device__ void cnot_s(float2* v) {
#pragma unroll
    for (int r = 0; r < 16; r++) {
        if (!((r >> C) & 1) || ((r >> T) & 1)) continue;
        int r2 = r | (1 << T);
        float2 t = v[r]; v[r] = v[r2]; v[r2] = t;
    }
}
__device__ void iter_regs_s(float2* v, const float2* sG) {
    crx_s<2, 1>(v, sG[0].x, sG[0].y);
    cry_s<3, 1>(v, sG[1].x, sG[1].y);
    crz_s<2, 0>(v, sG[2].x, sG[2].y);
    cry_s<3, 0>(v, sG[3].x, sG[3].y);
    ap_reg_s<3>(v, sG + 4);
    ap_reg_s<2>(v, sG + 8);
    ap_reg_s<1>(v, sG + 12);
    cnot_s<3, 2>(v);
    cnot_s<2, 1>(v);
    cnot_s<1, 3>(v);
    ap_reg_s<1>(v, sG + 16);
    ap_reg_s<2>(v, sG + 20);
    ap_reg_s<0>(v, sG + 24);
    cnot_s<1, 2>(v);
    cnot_s<2, 0>(v);
    cnot_s<0, 1>(v);
}

// ================= packed gate primitives =================
// state: R[8], I[8] ull. amp r = 2p + h: h=a2(bit0), p0=a1, p1=nb, p2=e.
template <int K, bool DN>
__device__ __forceinline__ void ap_p(ull* R, ull* I, const ull* U) {
    ull u0x = U[0], u0y = U[1], n0y = U[2], u1x = U[3], n1x = U[4],
        u1y = U[5], n1y = U[6], n0x = U[7];
#pragma unroll
    for (int p = 0; p < 8; p++) {
        if ((p >> K) & 1) continue;
        int q = p | (1 << K);
        ull ar = R[p], ai = I[p], br = R[q], bi = I[q];
        R[p] = fma2(u0x, ar, fma2(n0y, ai, fma2(u1x, br, mul2(n1y, bi))));
        I[p] = fma2(u0y, ar, fma2(u0x, ai, fma2(u1y, br, mul2(u1x, bi))));
        if (!DN) {  // SU(2): u2=-conj(u1), u3=conj(u0)
            R[q] = fma2(n1x, ar, fma2(n1y, ai, fma2(u0x, br, mul2(u0y, bi))));
            I[q] = fma2(u1y, ar, fma2(n1x, ai, fma2(n0y, br, mul2(u0x, bi))));
        } else {    // det=-1: u2=conj(u1), u3=-conj(u0)
            R[q] = fma2(u1x, ar, fma2(u1y, ai, fma2(n0x, br, mul2(n0y, bi))));
            I[q] = fma2(n1y, ar, fma2(u1x, ai, fma2(u0y, br, mul2(n0x, bi))));
        }
    }
}
template <int K>
__device__ __forceinline__ void swap_p(ull* A, int lane, int mask) {
    bool b = lane & mask;
#pragma unroll
    for (int p = 0; p < 8; p++) {
        if ((p >> K) & 1) continue;
        int q = p | (1 << K);
        ull send = b ? A[p] : A[q];
        ull recv = __shfl_xor_sync(0xffffffffu, send, mask);
        if (b) A[p] = recv; else A[q] = recv;
    }
}

__device__ __forceinline__ void iter_p(ull* R, ull* I, const ull* G) {
    { // CRX(nb->a1): pairs p in {2,6}
        ull c = G[62], s = G[63], ns = G[64];
#pragma unroll
        for (int p = 2; p < 8; p += 4) {
            int q = p + 1;
            ull ar = R[p], ai = I[p], br = R[q], bi = I[q];
            R[p] = fma2(c, ar, mul2(s,  bi)); I[p] = fma2(c, ai, mul2(ns, br));
            R[q] = fma2(c, br, mul2(s,  ai)); I[q] = fma2(c, bi, mul2(ns, ar));
        }
    }
    { // CRY(e->a1): pairs p in {4,6}
        ull c = G[65], s = G[66], ns = G[67];
#pragma unroll
        for (int p = 4; p < 8; p += 2) {
            int q = p + 1;
            ull ar = R[p], ai = I[p], br = R[q], bi = I[q];
            R[p] = fma2(c, ar, mul2(ns, br)); I[p] = fma2(c, ai, mul2(ns, bi));
            R[q] = fma2(c, br, mul2(s,  ar)); I[q] = fma2(c, bi, mul2(s,  ai));
        }
    }
    { // CRZ(nb->a2): p in {2,3,6,7}, phase per half
        ull c = G[68], sp = G[69], sn = G[70];
#pragma unroll
        for (int pp = 0; pp < 4; pp++) {
            int p = (pp < 2) ? 2 + pp : 4 + pp;
            ull t = R[p];
            R[p] = fma2(c, t, mul2(sp, I[p]));
            I[p] = fma2(c, I[p], mul2(sn, t));
        }
    }
    { // CRY(e->a2): p in {4..7}, target = half bit
        ull c = G[71], sm = G[72];
#pragma unroll
        for (int p = 4; p < 8; p++) {
            ull RS = hsw(R[p]), IS = hsw(I[p]);
            R[p] = fma2(c, R[p], mul2(sm, RS));
            I[p] = fma2(c, I[p], mul2(sm, IS));
        }
    }
    ap_p<2, false>(R, I, G + 0);    // Re on e(p2)
    ap_p<1, false>(R, I, G + 8);    // Rnb
    ap_p<0, false>(R, I, G + 16);   // Ra1
    // cnot(e->nb), cnot(nb->a1), cnot(a1->e): pure renames
    swp(R[4], R[6]); swp(R[5], R[7]); swp(I[4], I[6]); swp(I[5], I[7]);
    swp(R[2], R[3]); swp(R[6], R[7]); swp(I[2], I[3]); swp(I[6], I[7]);
    swp(R[1], R[5]); swp(R[3], R[7]); swp(I[1], I[5]); swp(I[3], I[7]);
    ap_p<0, false>(R, I, G + 24);   // Ra1p
    ap_p<1, false>(R, I, G + 32);   // Rnbp
    { // Ra2: full rot on half bit
        ull A = G[56], B = G[57], Gm = G[58], D = G[59], Ap = G[60], Bp = G[61];
#pragma unroll
        for (int p = 0; p < 8; p++) {
            ull RS = hsw(R[p]), IS = hsw(I[p]);
            ull nr = fma2(A,  R[p], fma2(B,  RS, fma2(Gm, I[p], mul2(D, IS))));
            ull ni = fma2(Ap, R[p], fma2(Bp, RS, fma2(A,  I[p], mul2(B, IS))));
            R[p] = nr; I[p] = ni;
        }
    }
    // cnot(a1->nb): renames
    swp(R[1], R[3]); swp(R[5], R[7]); swp(I[1], I[3]); swp(I[5], I[7]);
    // cnot(nb->a2): halfswap p in {2,3,6,7}
    R[2] = hsw(R[2]); R[3] = hsw(R[3]); R[6] = hsw(R[6]); R[7] = hsw(R[7]);
    I[2] = hsw(I[2]); I[3] = hsw(I[3]); I[6] = hsw(I[6]); I[7] = hsw(I[7]);
    // cnot(a2->a1): y-half swap pairs
#pragma unroll
    for (int p = 0; p < 8; p += 2) { yswp(R[p], R[p + 1]); yswp(I[p], I[p + 1]); }
}

// ---------------- gate precompute ----------------
__device__ void make_rot(const float* w, float2* m) {
    float phi = w[0], th = w[1], om = w[2];
    float c, s; sincosf(th * 0.5f, &s, &c);
    float sa, ca, sb, cb;
    sincosf((phi + om) * 0.5f, &sa, &ca);
    sincosf((phi - om) * 0.5f, &sb, &cb);
    m[0] = make_float2(c * ca, -c * sa);
    m[1] = make_float2(-s * cb, -s * sb);
    m[2] = make_float2(s * cb, -s * sb);
    m[3] = make_float2(c * ca, c * sa);
}
__device__ void cm2(const float2* A, const float2* B, float2* C) {
    C[0] = cadd(cmul(A[0], B[0]), cmul(A[1], B[2]));
    C[1] = cadd(cmul(A[0], B[1]), cmul(A[1], B[3]));
    C[2] = cadd(cmul(A[2], B[0]), cmul(A[3], B[2]));
    C[3] = cadd(cmul(A[2], B[1]), cmul(A[3], B[3]));
}
__device__ void prep_gates(const float* strong, const float* inits, const float* update) {
    float c, s;
    sincosf(inits[0] * 0.5f, &s, &c); g_gates[0] = make_float2(c, s);
    sincosf(inits[1] * 0.5f, &s, &c); g_gates[1] = make_float2(c, s);
    sincosf(inits[2] * 0.5f, &s, &c); g_gates[2] = make_float2(c, s);
    sincosf(inits[3] * 0.5f, &s, &c); g_gates[3] = make_float2(c, s);
    float2 M[4], Q[4];
    make_rot(strong + 0,  M); for (int k = 0; k < 4; k++) g_gates[4 + k]  = M[k];
    make_rot(strong + 3,  M); for (int k = 0; k < 4; k++) g_gates[8 + k]  = M[k];
    make_rot(strong + 6,  M); for (int k = 0; k < 4; k++) g_gates[12 + k] = M[k];
    make_rot(strong + 9,  M); for (int k = 0; k < 4; k++) g_gates[16 + k] = M[k];
    make_rot(strong + 12, M); for (int k = 0; k < 4; k++) g_gates[20 + k] = M[k];
    make_rot(strong + 15, M); for (int k = 0; k < 4; k++) g_gates[24 + k] = M[k];
    const float rh = 0.70710678118654752f;
    float2 H2[4];
    H2[0] = make_float2(rh, 0); H2[1] = make_float2(rh, 0);
    H2[2] = make_float2(rh, 0); H2[3] = make_float2(-rh, 0);
    make_rot(update + 0, M); cm2(H2, M, Q); for (int k = 0; k < 4; k++) g_gates[28 + k] = Q[k];
    make_rot(update + 3, M); cm2(H2, M, Q); for (int k = 0; k < 4; k++) g_gates[32 + k] = Q[k];
}
__device__ void pack8(const float2* m, ull* d) {
    d[0] = pk(m[0].x, m[0].x); d[1] = pk(m[0].y, m[0].y); d[2] = pk(-m[0].y, -m[0].y);
    d[3] = pk(m[1].x, m[1].x); d[4] = pk(-m[1].x, -m[1].x); d[5] = pk(m[1].y, m[1].y);
    d[6] = pk(-m[1].y, -m[1].y); d[7] = pk(-m[0].x, -m[0].x);
}
__device__ void pack_all() {
    pack8(&g_gates[4],  &g_gp[0]);    // Re
    pack8(&g_gates[8],  &g_gp[8]);    // Rnb
    pack8(&g_gates[12], &g_gp[16]);   // Ra1
    pack8(&g_gates[16], &g_gp[24]);   // Ra1p
    pack8(&g_gates[20], &g_gp[32]);   // Rnbp
    pack8(&g_gates[28], &g_gp[40]);   // Q3
    pack8(&g_gates[32], &g_gp[48]);   // Q1
    float2 m0 = g_gates[24], m1 = g_gates[25], m2 = g_gates[26], m3 = g_gates[27]; // Ra2
    g_gp[56] = pk(m0.x, m3.x);  g_gp[57] = pk(m1.x, m2.x);
    g_gp[58] = pk(-m0.y, -m3.y); g_gp[59] = pk(-m1.y, -m2.y);
    g_gp[60] = pk(m0.y, m3.y);  g_gp[61] = pk(m1.y, m2.y);
    float c, s;
    c = g_gates[0].x; s = g_gates[0].y;
    g_gp[62] = pk(c, c); g_gp[63] = pk(s, s); g_gp[64] = pk(-s, -s);
    c = g_gates[1].x; s = g_gates[1].y;
    g_gp[65] = pk(c, c); g_gp[66] = pk(s, s); g_gp[67] = pk(-s, -s);
    c = g_gates[2].x; s = g_gates[2].y;
    g_gp[68] = pk(c, c); g_gp[69] = pk(s, -s); g_gp[70] = pk(-s, s);
    c = g_gates[3].x; s = g_gates[3].y;
    g_gp[71] = pk(c, c); g_gp[72] = pk(-s, s);
}

// ---------------- K1: fused node+edge MLP (+ prep + packed tables) ----------------
template <int NI, bool IS_NODE>
__device__ __forceinline__ void mlp_row(const float* __restrict__ inp, int r,
                                        const float* sW1, const float* sb1,
                                        const float* sW2, const float* sb2) {
    float in[NI];
#pragma unroll
    for (int i = 0; i < NI; i++) in[i] = inp[r * NI + i];
    float o0 = sb2[0], o1 = sb2[1];
#pragma unroll 4
    for (int h = 0; h < 128; h++) {
        float a = sb1[h];
#pragma unroll
        for (int i = 0; i < NI; i++) a = fmaf(in[i], sW1[i * 128 + h], a);
        a = a > 0.f ? a : 0.01f * a;
        o0 = fmaf(a, sW2[2 * h], o0);
        o1 = fmaf(a, sW2[2 * h + 1], o1);
    }
    float t0 = tanhf(o0) * PI_F;
    float t1 = tanhf(o1) * PI_F;
    float sy, cy, sz, cz;
    sincosf(0.5f * t0, &sy, &cy);
    sincosf(0.5f * t1, &sz, &cz);
    float4 amps = make_float4(cy * cz, -cy * sz, sy * cz, sy * sz);
    if (IS_NODE) {
        g_x[2 * r] = t0; g_x[2 * r + 1] = t1;
        g_x4[r] = amps;
    } else {
        g_e4[r] = amps;
    }
}

__global__ void __launch_bounds__(128) mlp_fused_kernel(
    const float* __restrict__ node_feat,
    const float* __restrict__ Wn1, const float* __restrict__ bn1,
    const float* __restrict__ Wn2, const float* __restrict__ bn2,
    const float* __restrict__ edge_attr,
    const float* __restrict__ We1, const float* __restrict__ be1,
    const float* __restrict__ We2, const float* __restrict__ be2,
    const float* __restrict__ strong, const float* __restrict__ inits,
    const float* __restrict__ update) {
    __shared__ float sW1[8 * 128];
    __shared__ float sb1[128];
    __shared__ float sW2[256];
    __shared__ float sb2[2];
    int b = blockIdx.x, tid = threadIdx.x;
    bool isNode = (b < 32);
    const float* W1 = isNode ? Wn1 : We1;
    const float* b1 = isNode ? bn1 : be1;
    const float* W2 = isNode ? Wn2 : We2;
    const float* b2 = isNode ? bn2 : be2;
    int ni = isNode ? 8 : 4;
    for (int k = tid; k < ni * 128; k += 128) sW1[k] = W1[k];
    sb1[tid] = b1[tid];
    sW2[tid] = W2[tid]; sW2[128 + tid] = W2[128 + tid];
    if (tid < 2) sb2[tid] = b2[tid];

    if (b == 0) {
        if (tid < NUM_GRAPHS) {
            g_gsum[2 * tid] = 0.f; g_gsum[2 * tid + 1] = 0.f; g_gcnt[tid] = 0.f;
        }
        if (tid == 33) g_done = 0;
        if (tid == 32) prep_gates(strong, inits, update);
    }
    __syncthreads();

    if (b == 0) {
        if (tid == 48) pack_all();
        if (tid >= 64 && tid < 68) {   // W columns (scalar), store packed
            int k = tid - 64;
            float2 v[16];
#pragma unroll
            for (int r = 0; r < 16; r++) v[r] = make_float2(0.f, 0.f);
            v[((k >> 1) << 3) | ((k & 1) << 2)] = make_float2(1.f, 0.f);
            iter_regs_s(v, g_gates);
#pragma unroll
            for (int p = 0; p < 8; p++) {
                g_wp[k * 16 + p]     = pk(v[2 * p].x, v[2 * p + 1].x);
                g_wp[k * 16 + 8 + p] = pk(v[2 * p].y, v[2 * p + 1].y);
            }
        }
    }

    if (isNode)
        mlp_row<8, true>(node_feat, b * 128 + tid, sW1, sb1, sW2, sb2);
    else
        mlp_row<4, false>(edge_attr, (b - 32) * 128 + tid, sW1, sb1, sW2, sb2);
}

// ================= PQC kernel (packed f32x2) =================
__device__ __forceinline__ float2 pick(float4 a, int bit) {
    return bit ? make_float2(a.z, a.w) : make_float2(a.x, a.y);
}

__global__ void __launch_bounds__(128) pqc_kernel(
    const int* __restrict__ subgraphs, const int* __restrict__ edge_ids,
    const int* __restrict__ batch,
    const float* __restrict__ Wu1, const float* __restrict__ bu1,
    const float* __restrict__ Wu2, const float* __restrict__ bu2,
    const float* __restrict__ Wh1, const float* __restrict__ bh1,
    const float* __restrict__ Wh2, const float* __restrict__ bh2,
    float* __restrict__ out) {
    __shared__ ull sGP[73];
    __shared__ ull sWP[64];
    __shared__ float sW1[384];
    __shared__ float sb1[128];
    __shared__ float sW2[256];
    __shared__ float sb2[2];
    __shared__ float sAcc[NUM_GRAPHS * 3];
    __shared__ int sLast;
    int tid = threadIdx.x;
    for (int k = tid; k < 73; k += 128) sGP[k] = g_gp[k];
    for (int k = tid; k < 64; k += 128) sWP[k] = g_wp[k];
    for (int k = tid; k < 384; k += 128) sW1[k] = Wu1[k];
    sb1[tid] = bu1[tid];
    sW2[tid] = Wu2[tid]; sW2[128 + tid] = Wu2[128 + tid];
    if (tid < 2) sb2[tid] = bu2[tid];
    if (tid < NUM_GRAPHS * 3) sAcc[tid] = 0.f;
    __syncthreads();

    int lane = tid & 31;
    int s = blockIdx.x * 4 + (tid >> 5);

    int e0 = edge_ids[3 * s], e1 = edge_ids[3 * s + 1], e2 = edge_ids[3 * s + 2];
    int n0 = subgraphs[4 * s], n1 = subgraphs[4 * s + 1],
        n2 = subgraphs[4 * s + 2], n3 = subgraphs[4 * s + 3];

    float x0c = g_x[2 * n0], x1c = g_x[2 * n0 + 1];

    float2 lf = pick(g_e4[e1], (lane >> 4) & 1);
    lf = cmul(lf, pick(g_e4[e2], (lane >> 3) & 1));
    lf = cmul(lf, pick(g_x4[n0], (lane >> 2) & 1));
    lf = cmul(lf, pick(g_x4[n2], (lane >> 1) & 1));
    lf = cmul(lf, pick(g_x4[n3], lane & 1));
    float4 aw0 = g_e4[e0];
    float4 aw4 = g_x4[n1];

    float2 c0 = cmul(lf, cmul(pick(aw0, 0), pick(aw4, 0)));
    float2 c1 = cmul(lf, cmul(pick(aw0, 0), pick(aw4, 1)));
    float2 c2 = cmul(lf, cmul(pick(aw0, 1), pick(aw4, 0)));
    float2 c3 = cmul(lf, cmul(pick(aw0, 1), pick(aw4, 1)));

    // packed init: v = sum_k c_k * W_k
    ull R[8], I[8];
    {
        ull c0x = pk(c0.x, c0.x), c0y = pk(c0.y, c0.y), m0 = pk(-c0.y, -c0.y);
        ull c1x = pk(c1.x, c1.x), c1y = pk(c1.y, c1.y), m1 = pk(-c1.y, -c1.y);
        ull c2x = pk(c2.x, c2.x), c2y = pk(c2.y, c2.y), m2 = pk(-c2.y, -c2.y);
        ull c3x = pk(c3.x, c3.x), c3y = pk(c3.y, c3.y), m3 = pk(-c3.y, -c3.y);
#pragma unroll
        for (int p = 0; p < 8; p++) {
            ull w0r = sWP[p],      w0i = sWP[8 + p];
            ull w1r = sWP[16 + p], w1i = sWP[24 + p];
            ull w2r = sWP[32 + p], w2i = sWP[40 + p];
            ull w3r = sWP[48 + p], w3i = sWP[56 + p];
            R[p] = fma2(c0x, w0r, fma2(m0, w0i,
                   fma2(c1x, w1r, fma2(m1, w1i,
                   fma2(c2x, w2r, fma2(m2, w2i,
                   fma2(c3x, w3r, mul2(m3, w3i))))))));
            I[p] = fma2(c0y, w0r, fma2(c0x, w0i,
                   fma2(c1y, w1r, fma2(c1x, w1i,
                   fma2(c2y, w2r, fma2(c2x, w2i,
                   fma2(c3y, w3r, mul2(c3x, w3i))))))));
        }
    }

    // retarget: e(p2): w0<->w1(L4=16); nb(p1): w4<->w5(L1=2)
    swap_p<2>(R, lane, 16); swap_p<2>(I, lane, 16);
    swap_p<1>(R, lane, 2);  swap_p<1>(I, lane, 2);
    iter_p(R, I, sGP);                  // iteration 1
    swap_p<2>(R, lane, 8);  swap_p<2>(I, lane, 8);
    swap_p<1>(R, lane, 1);  swap_p<1>(I, lane, 1);
    iter_p(R, I, sGP);                  // iteration 2
    swap_p<2>(R, lane, 4);  swap_p<2>(I, lane, 4);   // p2 <- w3

    // final: Q3 on p2, Q1 on p0 (det -1 matrices)
    ap_p<2, true>(R, I, sGP + 40);
    ap_p<0, true>(R, I, sGP + 48);

    // aggr = sum_p sign(p2^p0) * (|both halves|^2)
    float part = 0.f;
#pragma unroll
    for (int p = 0; p < 8; p++) {
        ull t = fma2(R[p], R[p], mul2(I[p], I[p]));
        float x, y; upk(t, x, y);
        float v2 = x + y;
        part = (((p >> 2) ^ p) & 1) ? part - v2 : part + v2;
    }
#pragma unroll
    for (int o = 16; o; o >>= 1) part += __shfl_xor_sync(0xffffffffu, part, o);
    float aggr = part;

    // fused update MLP
    float o0 = 0.f, o1 = 0.f;
#pragma unroll
    for (int k = 0; k < 4; k++) {
        int h = lane + 32 * k;
        float a = fmaf(x0c, sW1[h],
                  fmaf(x1c, sW1[128 + h],
                  fmaf(aggr, sW1[256 + h], sb1[h])));
        a = a > 0.f ? a : 0.01f * a;
        o0 = fmaf(a, sW2[2 * h], o0);
        o1 = fmaf(a, sW2[2 * h + 1], o1);
    }
#pragma unroll
    for (int o = 16; o; o >>= 1) {
        o0 += __shfl_xor_sync(0xffffffffu, o0, o);
        o1 += __shfl_xor_sync(0xffffffffu, o1, o);
    }
    if (lane == 0) {
        o0 += sb2[0]; o1 += sb2[1];
        int gu = batch[n0];
        int gx = batch[s];
        atomicAdd(&sAcc[3 * gu + 0], o0);
        atomicAdd(&sAcc[3 * gu + 1], o1);
        atomicAdd(&sAcc[3 * gx + 0], g_x[2 * s]);
        atomicAdd(&sAcc[3 * gx + 1], g_x[2 * s + 1]);
        atomicAdd(&sAcc[3 * gx + 2], 1.f);
    }
    __syncthreads();

    if (tid < NUM_GRAPHS) {
        atomicAdd(&g_gsum[2 * tid],     sAcc[3 * tid + 0]);
        atomicAdd(&g_gsum[2 * tid + 1], sAcc[3 * tid + 1]);
        atomicAdd(&g_gcnt[tid],         sAcc[3 * tid + 2]);
        __threadfence();
    }
    __syncthreads();
    if (tid == 0) {
        int old = atomicAdd(&g_done, 1);
        sLast = (old == PQC_BLOCKS - 1);
        __threadfence();
    }
    __syncthreads();

    if (sLast && tid < NUM_GRAPHS) {
        int g = tid;
        float cnt = __ldcg(&g_gcnt[g]);
        float g0 = __ldcg(&g_gsum[2 * g]) / cnt;
        float g1 = __ldcg(&g_gsum[2 * g + 1]) / cnt;
        float h0 = g0 * Wh1[0] + g1 * Wh1[2] + bh1[0];
        float h1 = g0 * Wh1[1] + g1 * Wh1[3] + bh1[1];
        h0 = h0 > 0.f ? h0 : 0.01f * h0;
        h1 = h1 > 0.f ? h1 : 0.01f * h1;
        out[2 * g]     = h0 * Wh2[0] + h1 * Wh2[2] + bh2[0];
        out[2 * g + 1] = h0 * Wh2[1] + h1 * Wh2[3] + bh2[1];
    }
}

// ---------------- launch ----------------
extern "C" void kernel_launch(void* const* d_in, const int* in_sizes, int n_in,
                              void* d_out, int out_size) {
    const float* node_feat = (const float*)d_in[0];
    const float* edge_attr = (const float*)d_in[1];
    const float* Wn1 = (const float*)d_in[2];
    const float* bn1 = (const float*)d_in[3];
    const float* Wn2 = (const float*)d_in[4];
    const float* bn2 = (const float*)d_in[5];
    const float* We1 = (const float*)d_in[6];
    const float* be1 = (const float*)d_in[7];
    const float* We2 = (const float*)d_in[8];
    const float* be2 = (const float*)d_in[9];
    const float* strong = (const float*)d_in[10];
    const float* inits  = (const float*)d_in[11];
    const float* update = (const float*)d_in[12];
    const float* Wu1 = (const float*)d_in[13];
    const float* bu1 = (const float*)d_in[14];
    const float* Wu2 = (const float*)d_in[15];
    const float* bu2 = (const float*)d_in[16];
    const float* Wh1 = (const float*)d_in[17];
    const float* bh1 = (const float*)d_in[18];
    const float* Wh2 = (const float*)d_in[19];
    const float* bh2 = (const float*)d_in[20];
    const int* subgraphs = (const int*)d_in[21];
    const int* edge_ids  = (const int*)d_in[22];
    const int* batch     = (const int*)d_in[23];
    float* out = (float*)d_out;

    mlp_fused_kernel<<<128, 128>>>(node_feat, Wn1, bn1, Wn2, bn2,
                                   edge_attr, We1, be1, We2, be2,
                                   strong, inits, update);
    pqc_kernel<<<PQC_BLOCKS, 128>>>(subgraphs, edge_ids, batch,
                                    Wu1, bu1, Wu2, bu2,
                                    Wh1, bh1, Wh2, bh2, out);
}

// round 12
// speedup vs baseline: 1.1989x; 1.0598x over previous
#include <cuda_runtime.h>
#include <math.h>

#define PI_F 3.14159265358979323846f
#define N_NODES 4096
#define N_EDGES 12288
#define NUM_GRAPHS 16
#define PQC_BLOCKS 1024

typedef unsigned long long ull;

// ---------------- device scratch ----------------
__device__ float  g_x[N_NODES * 2];
__device__ float4 g_x4[N_NODES];
__device__ float4 g_e4[N_EDGES];
__device__ float2 g_gates[36];
__device__ ull    g_gp[73];
__device__ ull    g_wp[64];
__device__ float  g_gsum[NUM_GRAPHS * 2];
__device__ float  g_gcnt[NUM_GRAPHS];
__device__ int    g_done;

// ---------------- packed helpers ----------------
__device__ __forceinline__ ull pk(float x, float y) {
    ull r; asm("mov.b64 %0,{%1,%2};" : "=l"(r) : "f"(x), "f"(y)); return r;
}
__device__ __forceinline__ void upk(ull a, float& x, float& y) {
    asm("mov.b64 {%0,%1},%2;" : "=f"(x), "=f"(y) : "l"(a));
}
__device__ __forceinline__ ull fma2(ull a, ull b, ull c) {
    ull r; asm("fma.rn.f32x2 %0,%1,%2,%3;" : "=l"(r) : "l"(a), "l"(b), "l"(c)); return r;
}
__device__ __forceinline__ ull mul2(ull a, ull b) {
    ull r; asm("mul.rn.f32x2 %0,%1,%2;" : "=l"(r) : "l"(a), "l"(b)); return r;
}
__device__ __forceinline__ ull hsw(ull a) {
    float x, y; upk(a, x, y); return pk(y, x);
}
__device__ __forceinline__ void swp(ull& a, ull& b) { ull t = a; a = b; b = t; }
__device__ __forceinline__ void yswp(ull& A, ull& B) {
    float ax, ay, bx, by; upk(A, ax, ay); upk(B, bx, by);
    A = pk(ax, by); B = pk(bx, ay);
}

// ---------------- complex (scalar) helpers ----------------
__device__ __forceinline__ float2 cmul(float2 a, float2 b) {
    return make_float2(fmaf(a.x, b.x, -(a.y * b.y)), fmaf(a.x, b.y, a.y * b.x));
}
__device__ __forceinline__ float2 cfma(float2 a, float2 b, float2 c) {
    return make_float2(fmaf(a.x, b.x, fmaf(-a.y, b.y, c.x)),
                       fmaf(a.x, b.y, fmaf( a.y, b.x, c.y)));
}
__device__ __forceinline__ float2 cadd(float2 a, float2 b) {
    return make_float2(a.x + b.x, a.y + b.y);
}

// ================= scalar gate primitives (prep/W-columns only) =================
template <int J>
__device__ void ap_reg_s(float2* v, const float2* U) {
    float2 u0 = U[0], u1 = U[1], u2 = U[2], u3 = U[3];
#pragma unroll
    for (int r = 0; r < 16; r++) {
        if ((r >> J) & 1) continue;
        int r2 = r | (1 << J);
        float2 a = v[r], b = v[r2];
        v[r]  = cfma(u1, b, cmul(u0, a));
        v[r2] = cfma(u3, b, cmul(u2, a));
    }
}
template <int C, int T>
__device__ void crx_s(float2* v, float c, float s) {
#pragma unroll
    for (int r = 0; r < 16; r++) {
        if (!((r >> C) & 1) || ((r >> T) & 1)) continue;
        int r2 = r | (1 << T);
        float2 a = v[r], b = v[r2];
        v[r]  = make_float2(fmaf(c, a.x,  s * b.y), fmaf(c, a.y, -s * b.x));
        v[r2] = make_float2(fmaf(c, b.x,  s * a.y), fmaf(c, b.y, -s * a.x));
    }
}
template <int C, int T>
__device__ void cry_s(float2* v, float c, float s) {
#pragma unroll
    for (int r = 0; r < 16; r++) {
        if (!((r >> C) & 1) || ((r >> T) & 1)) continue;
        int r2 = r | (1 << T);
        float2 a = v[r], b = v[r2];
        v[r]  = make_float2(fmaf(c, a.x, -s * b.x), fmaf(c, a.y, -s * b.y));
        v[r2] = make_float2(fmaf(c, b.x,  s * a.x), fmaf(c, b.y,  s * a.y));
    }
}
template <int C, int T>
__device__ void crz_s(float2* v, float c, float s) {
#pragma unroll
    for (int r = 0; r < 16; r++) {
        if (!((r >> C) & 1)) continue;
        float sg = ((r >> T) & 1) ? -s : s;
        float2 a = v[r];
        v[r] = make_float2(fmaf(c, a.x, sg * a.y), fmaf(c, a.y, -sg * a.x));
    }
}
template <int C, int T>
__device__ void cnot_s(float2* v) {
#pragma unroll
    for (int r = 0; r < 16; r++) {
        if (!((r >> C) & 1) || ((r >> T) & 1)) continue;
        int r2 = r | (1 << T);
        float2 t = v[r]; v[r] = v[r2]; v[r2] = t;
    }
}
__device__ void iter_regs_s(float2* v, const float2* sG) {
    crx_s<2, 1>(v, sG[0].x, sG[0].y);
    cry_s<3, 1>(v, sG[1].x, sG[1].y);
    crz_s<2, 0>(v, sG[2].x, sG[2].y);
    cry_s<3, 0>(v, sG[3].x, sG[3].y);
    ap_reg_s<3>(v, sG + 4);
    ap_reg_s<2>(v, sG + 8);
    ap_reg_s<1>(v, sG + 12);
    cnot_s<3, 2>(v);
    cnot_s<2, 1>(v);
    cnot_s<1, 3>(v);
    ap_reg_s<1>(v, sG + 16);
    ap_reg_s<2>(v, sG + 20);
    ap_reg_s<0>(v, sG + 24);
    cnot_s<1, 2>(v);
    cnot_s<2, 0>(v);
    cnot_s<0, 1>(v);
}

// ================= packed gate primitives =================
template <int K, bool DN>
__device__ __forceinline__ void ap_p(ull* R, ull* I, const ull* U) {
    ull u0x = U[0], u0y = U[1], n0y = U[2], u1x = U[3], n1x = U[4],
        u1y = U[5], n1y = U[6], n0x = U[7];
#pragma unroll
    for (int p = 0; p < 8; p++) {
        if ((p >> K) & 1) continue;
        int q = p | (1 << K);
        ull ar = R[p], ai = I[p], br = R[q], bi = I[q];
        R[p] = fma2(u0x, ar, fma2(n0y, ai, fma2(u1x, br, mul2(n1y, bi))));
        I[p] = fma2(u0y, ar, fma2(u0x, ai, fma2(u1y, br, mul2(u1x, bi))));
        if (!DN) {
            R[q] = fma2(n1x, ar, fma2(n1y, ai, fma2(u0x, br, mul2(u0y, bi))));
            I[q] = fma2(u1y, ar, fma2(n1x, ai, fma2(n0y, br, mul2(u0x, bi))));
        } else {
            R[q] = fma2(u1x, ar, fma2(u1y, ai, fma2(n0x, br, mul2(n0y, bi))));
            I[q] = fma2(n1y, ar, fma2(u1x, ai, fma2(u0y, br, mul2(n0x, bi))));
        }
    }
}
template <int K>
__device__ __forceinline__ void swap_p(ull* A, int lane, int mask) {
    bool b = lane & mask;
#pragma unroll
    for (int p = 0; p < 8; p++) {
        if ((p >> K) & 1) continue;
        int q = p | (1 << K);
        ull send = b ? A[p] : A[q];
        ull recv = __shfl_xor_sync(0xffffffffu, send, mask);
        if (b) A[p] = recv; else A[q] = recv;
    }
}

__device__ __forceinline__ void iter_p(ull* R, ull* I, const ull* G) {
    {
        ull c = G[62], s = G[63], ns = G[64];
#pragma unroll
        for (int p = 2; p < 8; p += 4) {
            int q = p + 1;
            ull ar = R[p], ai = I[p], br = R[q], bi = I[q];
            R[p] = fma2(c, ar, mul2(s,  bi)); I[p] = fma2(c, ai, mul2(ns, br));
            R[q] = fma2(c, br, mul2(s,  ai)); I[q] = fma2(c, bi, mul2(ns, ar));
        }
    }
    {
        ull c = G[65], s = G[66], ns = G[67];
#pragma unroll
        for (int p = 4; p < 8; p += 2) {
            int q = p + 1;
            ull ar = R[p], ai = I[p], br = R[q], bi = I[q];
            R[p] = fma2(c, ar, mul2(ns, br)); I[p] = fma2(c, ai, mul2(ns, bi));
            R[q] = fma2(c, br, mul2(s,  ar)); I[q] = fma2(c, bi, mul2(s,  ai));
        }
    }
    {
        ull c = G[68], sp = G[69], sn = G[70];
#pragma unroll
        for (int pp = 0; pp < 4; pp++) {
            int p = (pp < 2) ? 2 + pp : 4 + pp;
            ull t = R[p];
            R[p] = fma2(c, t, mul2(sp, I[p]));
            I[p] = fma2(c, I[p], mul2(sn, t));
        }
    }
    {
        ull c = G[71], sm = G[72];
#pragma unroll
        for (int p = 4; p < 8; p++) {
            ull RS = hsw(R[p]), IS = hsw(I[p]);
            R[p] = fma2(c, R[p], mul2(sm, RS));
            I[p] = fma2(c, I[p], mul2(sm, IS));
        }
    }
    ap_p<2, false>(R, I, G + 0);
    ap_p<1, false>(R, I, G + 8);
    ap_p<0, false>(R, I, G + 16);
    swp(R[4], R[6]); swp(R[5], R[7]); swp(I[4], I[6]); swp(I[5], I[7]);
    swp(R[2], R[3]); swp(R[6], R[7]); swp(I[2], I[3]); swp(I[6], I[7]);
    swp(R[1], R[5]); swp(R[3], R[7]); swp(I[1], I[5]); swp(I[3], I[7]);
    ap_p<0, false>(R, I, G + 24);
    ap_p<1, false>(R, I, G + 32);
    {
        ull A = G[56], B = G[57], Gm = G[58], D = G[59], Ap = G[60], Bp = G[61];
#pragma unroll
        for (int p = 0; p < 8; p++) {
            ull RS = hsw(R[p]), IS = hsw(I[p]);
            ull nr = fma2(A,  R[p], fma2(B,  RS, fma2(Gm, I[p], mul2(D, IS))));
            ull ni = fma2(Ap, R[p], fma2(Bp, RS, fma2(A,  I[p], mul2(B, IS))));
            R[p] = nr; I[p] = ni;
        }
    }
    swp(R[1], R[3]); swp(R[5], R[7]); swp(I[1], I[3]); swp(I[5], I[7]);
    R[2] = hsw(R[2]); R[3] = hsw(R[3]); R[6] = hsw(R[6]); R[7] = hsw(R[7]);
    I[2] = hsw(I[2]); I[3] = hsw(I[3]); I[6] = hsw(I[6]); I[7] = hsw(I[7]);
#pragma unroll
    for (int p = 0; p < 8; p += 2) { yswp(R[p], R[p + 1]); yswp(I[p], I[p + 1]); }
}

// ---------------- gate precompute ----------------
__device__ void make_rot(const float* w, float2* m) {
    float phi = w[0], th = w[1], om = w[2];
    float c, s; sincosf(th * 0.5f, &s, &c);
    float sa, ca, sb, cb;
    sincosf((phi + om) * 0.5f, &sa, &ca);
    sincosf((phi - om) * 0.5f, &sb, &cb);
    m[0] = make_float2(c * ca, -c * sa);
    m[1] = make_float2(-s * cb, -s * sb);
    m[2] = make_float2(s * cb, -s * sb);
    m[3] = make_float2(c * ca, c * sa);
}
__device__ void cm2(const float2* A, const float2* B, float2* C) {
    C[0] = cadd(cmul(A[0], B[0]), cmul(A[1], B[2]));
    C[1] = cadd(cmul(A[0], B[1]), cmul(A[1], B[3]));
    C[2] = cadd(cmul(A[2], B[0]), cmul(A[3], B[2]));
    C[3] = cadd(cmul(A[2], B[1]), cmul(A[3], B[3]));
}
__device__ void prep_gates(const float* strong, const float* inits, const float* update) {
    float c, s;
    sincosf(inits[0] * 0.5f, &s, &c); g_gates[0] = make_float2(c, s);
    sincosf(inits[1] * 0.5f, &s, &c); g_gates[1] = make_float2(c, s);
    sincosf(inits[2] * 0.5f, &s, &c); g_gates[2] = make_float2(c, s);
    sincosf(inits[3] * 0.5f, &s, &c); g_gates[3] = make_float2(c, s);
    float2 M[4], Q[4];
    make_rot(strong + 0,  M); for (int k = 0; k < 4; k++) g_gates[4 + k]  = M[k];
    make_rot(strong + 3,  M); for (int k = 0; k < 4; k++) g_gates[8 + k]  = M[k];
    make_rot(strong + 6,  M); for (int k = 0; k < 4; k++) g_gates[12 + k] = M[k];
    make_rot(strong + 9,  M); for (int k = 0; k < 4; k++) g_gates[16 + k] = M[k];
    make_rot(strong + 12, M); for (int k = 0; k < 4; k++) g_gates[20 + k] = M[k];
    make_rot(strong + 15, M); for (int k = 0; k < 4; k++) g_gates[24 + k] = M[k];
    const float rh = 0.70710678118654752f;
    float2 H2[4];
    H2[0] = make_float2(rh, 0); H2[1] = make_float2(rh, 0);
    H2[2] = make_float2(rh, 0); H2[3] = make_float2(-rh, 0);
    make_rot(update + 0, M); cm2(H2, M, Q); for (int k = 0; k < 4; k++) g_gates[28 + k] = Q[k];
    make_rot(update + 3, M); cm2(H2, M, Q); for (int k = 0; k < 4; k++) g_gates[32 + k] = Q[k];
}
__device__ void pack8(const float2* m, ull* d) {
    d[0] = pk(m[0].x, m[0].x); d[1] = pk(m[0].y, m[0].y); d[2] = pk(-m[0].y, -m[0].y);
    d[3] = pk(m[1].x, m[1].x); d[4] = pk(-m[1].x, -m[1].x); d[5] = pk(m[1].y, m[1].y);
    d[6] = pk(-m[1].y, -m[1].y); d[7] = pk(-m[0].x, -m[0].x);
}
__device__ void pack_all() {
    pack8(&g_gates[4],  &g_gp[0]);
    pack8(&g_gates[8],  &g_gp[8]);
    pack8(&g_gates[12], &g_gp[16]);
    pack8(&g_gates[16], &g_gp[24]);
    pack8(&g_gates[20], &g_gp[32]);
    pack8(&g_gates[28], &g_gp[40]);
    pack8(&g_gates[32], &g_gp[48]);
    float2 m0 = g_gates[24], m1 = g_gates[25], m2 = g_gates[26], m3 = g_gates[27];
    g_gp[56] = pk(m0.x, m3.x);  g_gp[57] = pk(m1.x, m2.x);
    g_gp[58] = pk(-m0.y, -m3.y); g_gp[59] = pk(-m1.y, -m2.y);
    g_gp[60] = pk(m0.y, m3.y);  g_gp[61] = pk(m1.y, m2.y);
    float c, s;
    c = g_gates[0].x; s = g_gates[0].y;
    g_gp[62] = pk(c, c); g_gp[63] = pk(s, s); g_gp[64] = pk(-s, -s);
    c = g_gates[1].x; s = g_gates[1].y;
    g_gp[65] = pk(c, c); g_gp[66] = pk(s, s); g_gp[67] = pk(-s, -s);
    c = g_gates[2].x; s = g_gates[2].y;
    g_gp[68] = pk(c, c); g_gp[69] = pk(s, -s); g_gp[70] = pk(-s, s);
    c = g_gates[3].x; s = g_gates[3].y;
    g_gp[71] = pk(c, c); g_gp[72] = pk(-s, s);
}

// ---------------- K1: node/edge MLP, 8 threads per row (+ prep + packed tables) ----------------
template <int NI, bool IS_NODE>
__device__ __forceinline__ void mlp_phase(const float* __restrict__ inp, int row, int k8,
                                          const float* sMW1, const float* sMb1,
                                          const float* sMW2, const float* sMb2) {
    float in[NI];
#pragma unroll
    for (int i = 0; i < NI; i++) in[i] = inp[row * NI + i];
    float o0 = 0.f, o1 = 0.f;
#pragma unroll
    for (int j = 0; j < 16; j++) {
        int h = k8 + 8 * j;
        float a = sMb1[h];
#pragma unroll
        for (int i = 0; i < NI; i++) a = fmaf(in[i], sMW1[i * 128 + h], a);
        a = a > 0.f ? a : 0.01f * a;
        o0 = fmaf(a, sMW2[2 * h], o0);
        o1 = fmaf(a, sMW2[2 * h + 1], o1);
    }
#pragma unroll
    for (int o = 1; o < 8; o <<= 1) {
        o0 += __shfl_xor_sync(0xffffffffu, o0, o);
        o1 += __shfl_xor_sync(0xffffffffu, o1, o);
    }
    if (k8 == 0) {
        o0 += sMb2[0]; o1 += sMb2[1];
        float t0 = tanhf(o0) * PI_F;
        float t1 = tanhf(o1) * PI_F;
        float sy, cy, sz, cz;
        sincosf(0.5f * t0, &sy, &cy);
        sincosf(0.5f * t1, &sz, &cz);
        float4 amps = make_float4(cy * cz, -cy * sz, sy * cz, sy * sz);
        if (IS_NODE) {
            g_x[2 * row] = t0; g_x[2 * row + 1] = t1;
            g_x4[row] = amps;
        } else {
            g_e4[row] = amps;
        }
    }
}

__global__ void __launch_bounds__(128) mlp_fused_kernel(
    const float* __restrict__ node_feat,
    const float* __restrict__ Wn1, const float* __restrict__ bn1,
    const float* __restrict__ Wn2, const float* __restrict__ bn2,
    const float* __restrict__ edge_attr,
    const float* __restrict__ We1, const float* __restrict__ be1,
    const float* __restrict__ We2, const float* __restrict__ be2,
    const float* __restrict__ strong, const float* __restrict__ inits,
    const float* __restrict__ update) {
    __shared__ float sW1[8 * 128];
    __shared__ float sb1[128];
    __shared__ float sW2[256];
    __shared__ float sb2[2];
    int b = blockIdx.x, tid = threadIdx.x;
    bool isNode = (b < 256);
    const float* W1 = isNode ? Wn1 : We1;
    const float* b1 = isNode ? bn1 : be1;
    const float* W2 = isNode ? Wn2 : We2;
    const float* b2 = isNode ? bn2 : be2;
    int ni = isNode ? 8 : 4;
    for (int k = tid; k < ni * 128; k += 128) sW1[k] = W1[k];
    sb1[tid] = b1[tid];
    sW2[tid] = W2[tid]; sW2[128 + tid] = W2[128 + tid];
    if (tid < 2) sb2[tid] = b2[tid];

    if (b == 0) {
        if (tid < NUM_GRAPHS) {
            g_gsum[2 * tid] = 0.f; g_gsum[2 * tid + 1] = 0.f; g_gcnt[tid] = 0.f;
        }
        if (tid == 33) g_done = 0;
        if (tid == 32) prep_gates(strong, inits, update);
    }
    __syncthreads();

    if (b == 0) {
        if (tid == 48) pack_all();
        if (tid >= 64 && tid < 68) {
            int k = tid - 64;
            float2 v[16];
#pragma unroll
            for (int r = 0; r < 16; r++) v[r] = make_float2(0.f, 0.f);
            v[((k >> 1) << 3) | ((k & 1) << 2)] = make_float2(1.f, 0.f);
            iter_regs_s(v, g_gates);
#pragma unroll
            for (int p = 0; p < 8; p++) {
                g_wp[k * 16 + p]     = pk(v[2 * p].x, v[2 * p + 1].x);
                g_wp[k * 16 + 8 + p] = pk(v[2 * p].y, v[2 * p + 1].y);
            }
        }
    }

    int k8 = tid & 7;
    int rowLocal = tid >> 3;   // 0..15
    if (isNode)
        mlp_phase<8, true>(node_feat, b * 16 + rowLocal, k8, sW1, sb1, sW2, sb2);
    else
        mlp_phase<4, false>(edge_attr, (b - 256) * 16 + rowLocal, k8, sW1, sb1, sW2, sb2);
}

// ================= PQC kernel (packed f32x2) =================
__device__ __forceinline__ float2 pick(float4 a, int bit) {
    return bit ? make_float2(a.z, a.w) : make_float2(a.x, a.y);
}

__global__ void __launch_bounds__(128, 6) pqc_kernel(
    const int* __restrict__ subgraphs, const int* __restrict__ edge_ids,
    const int* __restrict__ batch,
    const float* __restrict__ Wu1, const float* __restrict__ bu1,
    const float* __restrict__ Wu2, const float* __restrict__ bu2,
    const float* __restrict__ Wh1, const float* __restrict__ bh1,
    const float* __restrict__ Wh2, const float* __restrict__ bh2,
    float* __restrict__ out) {
    __shared__ ull sGP[73];
    __shared__ ull sWP[64];
    __shared__ float sW1[384];
    __shared__ float sb1[128];
    __shared__ float sW2[256];
    __shared__ float sb2[2];
    __shared__ float sAcc[NUM_GRAPHS * 3];
    __shared__ int sLast;
    int tid = threadIdx.x;
    for (int k = tid; k < 73; k += 128) sGP[k] = g_gp[k];
    for (int k = tid; k < 64; k += 128) sWP[k] = g_wp[k];
    for (int k = tid; k < 384; k += 128) sW1[k] = Wu1[k];
    sb1[tid] = bu1[tid];
    sW2[tid] = Wu2[tid]; sW2[128 + tid] = Wu2[128 + tid];
    if (tid < 2) sb2[tid] = bu2[tid];
    if (tid < NUM_GRAPHS * 3) sAcc[tid] = 0.f;
    __syncthreads();

    int lane = tid & 31;
    int s = blockIdx.x * 4 + (tid >> 5);

    int e0 = edge_ids[3 * s], e1 = edge_ids[3 * s + 1], e2 = edge_ids[3 * s + 2];
    int n0 = subgraphs[4 * s], n1 = subgraphs[4 * s + 1],
        n2 = subgraphs[4 * s + 2], n3 = subgraphs[4 * s + 3];

    float x0c = g_x[2 * n0], x1c = g_x[2 * n0 + 1];

    float2 lf = pick(g_e4[e1], (lane >> 4) & 1);
    lf = cmul(lf, pick(g_e4[e2], (lane >> 3) & 1));
    lf = cmul(lf, pick(g_x4[n0], (lane >> 2) & 1));
    lf = cmul(lf, pick(g_x4[n2], (lane >> 1) & 1));
    lf = cmul(lf, pick(g_x4[n3], lane & 1));
    float4 aw0 = g_e4[e0];
    float4 aw4 = g_x4[n1];

    float2 c0 = cmul(lf, cmul(pick(aw0, 0), pick(aw4, 0)));
    float2 c1 = cmul(lf, cmul(pick(aw0, 0), pick(aw4, 1)));
    float2 c2 = cmul(lf, cmul(pick(aw0, 1), pick(aw4, 0)));
    float2 c3 = cmul(lf, cmul(pick(aw0, 1), pick(aw4, 1)));

    ull R[8], I[8];
    {
        ull c0x = pk(c0.x, c0.x), c0y = pk(c0.y, c0.y), m0 = pk(-c0.y, -c0.y);
        ull c1x = pk(c1.x, c1.x), c1y = pk(c1.y, c1.y), m1 = pk(-c1.y, -c1.y);
        ull c2x = pk(c2.x, c2.x), c2y = pk(c2.y, c2.y), m2 = pk(-c2.y, -c2.y);
        ull c3x = pk(c3.x, c3.x), c3y = pk(c3.y, c3.y), m3 = pk(-c3.y, -c3.y);
#pragma unroll
        for (int p = 0; p < 8; p++) {
            ull w0r = sWP[p],      w0i = sWP[8 + p];
            ull w1r = sWP[16 + p], w1i = sWP[24 + p];
            ull w2r = sWP[32 + p], w2i = sWP[40 + p];
            ull w3r = sWP[48 + p], w3i = sWP[56 + p];
            R[p] = fma2(c0x, w0r, fma2(m0, w0i,
                   fma2(c1x, w1r, fma2(m1, w1i,
                   fma2(c2x, w2r, fma2(m2, w2i,
                   fma2(c3x, w3r, mul2(m3, w3i))))))));
            I[p] = fma2(c0y, w0r, fma2(c0x, w0i,
                   fma2(c1y, w1r, fma2(c1x, w1i,
                   fma2(c2y, w2r, fma2(c2x, w2i,
                   fma2(c3y, w3r, mul2(c3x, w3i))))))));
        }
    }

    swap_p<2>(R, lane, 16); swap_p<2>(I, lane, 16);
    swap_p<1>(R, lane, 2);  swap_p<1>(I, lane, 2);
    iter_p(R, I, sGP);
    swap_p<2>(R, lane, 8);  swap_p<2>(I, lane, 8);
    swap_p<1>(R, lane, 1);  swap_p<1>(I, lane, 1);
    iter_p(R, I, sGP);
    swap_p<2>(R, lane, 4);  swap_p<2>(I, lane, 4);

    ap_p<2, true>(R, I, sGP + 40);
    ap_p<0, true>(R, I, sGP + 48);

    float part = 0.f;
#pragma unroll
    for (int p = 0; p < 8; p++) {
        ull t = fma2(R[p], R[p], mul2(I[p], I[p]));
        float x, y; upk(t, x, y);
        float v2 = x + y;
        part = (((p >> 2) ^ p) & 1) ? part - v2 : part + v2;
    }
#pragma unroll
    for (int o = 16; o; o >>= 1) part += __shfl_xor_sync(0xffffffffu, part, o);
    float aggr = part;

    float o0 = 0.f, o1 = 0.f;
#pragma unroll
    for (int k = 0; k < 4; k++) {
        int h = lane + 32 * k;
        float a = fmaf(x0c, sW1[h],
                  fmaf(x1c, sW1[128 + h],
                  fmaf(aggr, sW1[256 + h], sb1[h])));
        a = a > 0.f ? a : 0.01f * a;
        o0 = fmaf(a, sW2[2 * h], o0);
        o1 = fmaf(a, sW2[2 * h + 1], o1);
    }
#pragma unroll
    for (int o = 16; o; o >>= 1) {
        o0 += __shfl_xor_sync(0xffffffffu, o0, o);
        o1 += __shfl_xor_sync(0xffffffffu, o1, o);
    }
    if (lane == 0) {
        o0 += sb2[0]; o1 += sb2[1];
        int gu = batch[n0];
        int gx = batch[s];
        atomicAdd(&sAcc[3 * gu + 0], o0);
        atomicAdd(&sAcc[3 * gu + 1], o1);
        atomicAdd(&sAcc[3 * gx + 0], g_x[2 * s]);
        atomicAdd(&sAcc[3 * gx + 1], g_x[2 * s + 1]);
        atomicAdd(&sAcc[3 * gx + 2], 1.f);
    }
    __syncthreads();

    if (tid < NUM_GRAPHS) {
        atomicAdd(&g_gsum[2 * tid],     sAcc[3 * tid + 0]);
        atomicAdd(&g_gsum[2 * tid + 1], sAcc[3 * tid + 1]);
        atomicAdd(&g_gcnt[tid],         sAcc[3 * tid + 2]);
        __threadfence();
    }
    __syncthreads();
    if (tid == 0) {
        int old = atomicAdd(&g_done, 1);
        sLast = (old == PQC_BLOCKS - 1);
        __threadfence();
    }
    __syncthreads();

    if (sLast && tid < NUM_GRAPHS) {
        int g = tid;
        float cnt = __ldcg(&g_gcnt[g]);
        float g0 = __ldcg(&g_gsum[2 * g]) / cnt;
        float g1 = __ldcg(&g_gsum[2 * g + 1]) / cnt;
        float h0 = g0 * Wh1[0] + g1 * Wh1[2] + bh1[0];
        float h1 = g0 * Wh1[1] + g1 * Wh1[3] + bh1[1];
        h0 = h0 > 0.f ? h0 : 0.01f * h0;
        h1 = h1 > 0.f ? h1 : 0.01f * h1;
        out[2 * g]     = h0 * Wh2[0] + h1 * Wh2[2] + bh2[0];
        out[2 * g + 1] = h0 * Wh2[1] + h1 * Wh2[3] + bh2[1];
    }
}

// ---------------- launch ----------------
extern "C" void kernel_launch(void* const* d_in, const int* in_sizes, int n_in,
                              void* d_out, int out_size) {
    const float* node_feat = (const float*)d_in[0];
    const float* edge_attr = (const float*)d_in[1];
    const float* Wn1 = (const float*)d_in[2];
    const float* bn1 = (const float*)d_in[3];
    const float* Wn2 = (const float*)d_in[4];
    const float* bn2 = (const float*)d_in[5];
    const float* We1 = (const float*)d_in[6];
    const float* be1 = (const float*)d_in[7];
    const float* We2 = (const float*)d_in[8];
    const float* be2 = (const float*)d_in[9];
    const float* strong = (const float*)d_in[10];
    const float* inits  = (const float*)d_in[11];
    const float* update = (const float*)d_in[12];
    const float* Wu1 = (const float*)d_in[13];
    const float* bu1 = (const float*)d_in[14];
    const float* Wu2 = (const float*)d_in[15];
    const float* bu2 = (const float*)d_in[16];
    const float* Wh1 = (const float*)d_in[17];
    const float* bh1 = (const float*)d_in[18];
    const float* Wh2 = (const float*)d_in[19];
    const float* bh2 = (const float*)d_in[20];
    const int* subgraphs = (const int*)d_in[21];
    const int* edge_ids  = (const int*)d_in[22];
    const int* batch     = (const int*)d_in[23];
    float* out = (float*)d_out;

    mlp_fused_kernel<<<1024, 128>>>(node_feat, Wn1, bn1, Wn2, bn2,
                                    edge_attr, We1, be1, We2, be2,
                                    strong, inits, update);
    pqc_kernel<<<PQC_BLOCKS, 128>>>(subgraphs, edge_ids, batch,
                                    Wu1, bu1, Wu2, bu2,
                                    Wh1, bh1, Wh2, bh2, out);
}

// round 13
// speedup vs baseline: 1.3007x; 1.0849x over previous
#include <cuda_runtime.h>
#include <math.h>

#define PI_F 3.14159265358979323846f
#define N_NODES 4096
#define N_EDGES 12288
#define NUM_GRAPHS 16
#define PQC_BLOCKS 1024

typedef unsigned long long ull;

// ---------------- device scratch ----------------
__device__ float  g_x[N_NODES * 2];
__device__ float4 g_x4[N_NODES];
__device__ float4 g_e4[N_EDGES];
__device__ float2 g_gates[36];
__device__ ull    g_gp[73];
__device__ ull    g_wp[64];
__device__ float  g_gsum[NUM_GRAPHS * 2];
__device__ float  g_gcnt[NUM_GRAPHS];
__device__ int    g_done;

// ---------------- packed helpers ----------------
__device__ __forceinline__ ull pk(float x, float y) {
    ull r; asm("mov.b64 %0,{%1,%2};" : "=l"(r) : "f"(x), "f"(y)); return r;
}
__device__ __forceinline__ void upk(ull a, float& x, float& y) {
    asm("mov.b64 {%0,%1},%2;" : "=f"(x), "=f"(y) : "l"(a));
}
__device__ __forceinline__ ull fma2(ull a, ull b, ull c) {
    ull r; asm("fma.rn.f32x2 %0,%1,%2,%3;" : "=l"(r) : "l"(a), "l"(b), "l"(c)); return r;
}
__device__ __forceinline__ ull mul2(ull a, ull b) {
    ull r; asm("mul.rn.f32x2 %0,%1,%2;" : "=l"(r) : "l"(a), "l"(b)); return r;
}
__device__ __forceinline__ ull hsw(ull a) {
    float x, y; upk(a, x, y); return pk(y, x);
}
__device__ __forceinline__ void swp(ull& a, ull& b) { ull t = a; a = b; b = t; }
__device__ __forceinline__ void yswp(ull& A, ull& B) {
    float ax, ay, bx, by; upk(A, ax, ay); upk(B, bx, by);
    A = pk(ax, by); B = pk(bx, ay);
}

// ---------------- complex (scalar) helpers ----------------
__device__ __forceinline__ float2 cmul(float2 a, float2 b) {
    return make_float2(fmaf(a.x, b.x, -(a.y * b.y)), fmaf(a.x, b.y, a.y * b.x));
}
__device__ __forceinline__ float2 cfma(float2 a, float2 b, float2 c) {
    return make_float2(fmaf(a.x, b.x, fmaf(-a.y, b.y, c.x)),
                       fmaf(a.x, b.y, fmaf( a.y, b.x, c.y)));
}
__device__ __forceinline__ float2 cadd(float2 a, float2 b) {
    return make_float2(a.x + b.x, a.y + b.y);
}

// ================= scalar gate primitives (prep/W-columns only) =================
template <int J>
__device__ void ap_reg_s(float2* v, const float2* U) {
    float2 u0 = U[0], u1 = U[1], u2 = U[2], u3 = U[3];
#pragma unroll
    for (int r = 0; r < 16; r++) {
        if ((r >> J) & 1) continue;
        int r2 = r | (1 << J);
        float2 a = v[r], b = v[r2];
        v[r]  = cfma(u1, b, cmul(u0, a));
        v[r2] = cfma(u3, b, cmul(u2, a));
    }
}
template <int C, int T>
__device__ void crx_s(float2* v, float c, float s) {
#pragma unroll
    for (int r = 0; r < 16; r++) {
        if (!((r >> C) & 1) || ((r >> T) & 1)) continue;
        int r2 = r | (1 << T);
        float2 a = v[r], b = v[r2];
        v[r]  = make_float2(fmaf(c, a.x,  s * b.y), fmaf(c, a.y, -s * b.x));
        v[r2] = make_float2(fmaf(c, b.x,  s * a.y), fmaf(c, b.y, -s * a.x));
    }
}
template <int C, int T>
__device__ void cry_s(float2* v, float c, float s) {
#pragma unroll
    for (int r = 0; r < 16; r++) {
        if (!((r >> C) & 1) || ((r >> T) & 1)) continue;
        int r2 = r | (1 << T);
        float2 a = v[r], b = v[r2];
        v[r]  = make_float2(fmaf(c, a.x, -s * b.x), fmaf(c, a.y, -s * b.y));
        v[r2] = make_float2(fmaf(c, b.x,  s * a.x), fmaf(c, b.y,  s * a.y));
    }
}
template <int C, int T>
__device__ void crz_s(float2* v, float c, float s) {
#pragma unroll
    for (int r = 0; r < 16; r++) {
        if (!((r >> C) & 1)) continue;
        float sg = ((r >> T) & 1) ? -s : s;
        float2 a = v[r];
        v[r] = make_float2(fmaf(c, a.x, sg * a.y), fmaf(c, a.y, -sg * a.x));
    }
}
template <int C, int T>
__device__ void cnot_s(float2* v) {
#pragma unroll
    for (int r = 0; r < 16; r++) {
        if (!((r >> C) & 1) || ((r >> T) & 1)) continue;
        int r2 = r | (1 << T);
        float2 t = v[r]; v[r] = v[r2]; v[r2] = t;
    }
}
__device__ void iter_regs_s(float2* v, const float2* sG) {
    crx_s<2, 1>(v, sG[0].x, sG[0].y);
    cry_s<3, 1>(v, sG[1].x, sG[1].y);
    crz_s<2, 0>(v, sG[2].x, sG[2].y);
    cry_s<3, 0>(v, sG[3].x, sG[3].y);
    ap_reg_s<3>(v, sG + 4);
    ap_reg_s<2>(v, sG + 8);
    ap_reg_s<1>(v, sG + 12);
    cnot_s<3, 2>(v);
    cnot_s<2, 1>(v);
    cnot_s<1, 3>(v);
    ap_reg_s<1>(v, sG + 16);
    ap_reg_s<2>(v, sG + 20);
    ap_reg_s<0>(v, sG + 24);
    cnot_s<1, 2>(v);
    cnot_s<2, 0>(v);
    cnot_s<0, 1>(v);
}

// ================= packed gate primitives =================
template <int K, bool DN>
__device__ __forceinline__ void ap_p(ull* R, ull* I, const ull* U) {
    ull u0x = U[0], u0y = U[1], n0y = U[2], u1x = U[3], n1x = U[4],
        u1y = U[5], n1y = U[6], n0x = U[7];
#pragma unroll
    for (int p = 0; p < 8; p++) {
        if ((p >> K) & 1) continue;
        int q = p | (1 << K);
        ull ar = R[p], ai = I[p], br = R[q], bi = I[q];
        R[p] = fma2(u0x, ar, fma2(n0y, ai, fma2(u1x, br, mul2(n1y, bi))));
        I[p] = fma2(u0y, ar, fma2(u0x, ai, fma2(u1y, br, mul2(u1x, bi))));
        if (!DN) {
            R[q] = fma2(n1x, ar, fma2(n1y, ai, fma2(u0x, br, mul2(u0y, bi))));
            I[q] = fma2(u1y, ar, fma2(n1x, ai, fma2(n0y, br, mul2(u0x, bi))));
        } else {
            R[q] = fma2(u1x, ar, fma2(u1y, ai, fma2(n0x, br, mul2(n0y, bi))));
            I[q] = fma2(n1y, ar, fma2(u1x, ai, fma2(u0y, br, mul2(n0x, bi))));
        }
    }
}
template <int K>
__device__ __forceinline__ void swap_p(ull* A, int lane, int mask) {
    bool b = lane & mask;
#pragma unroll
    for (int p = 0; p < 8; p++) {
        if ((p >> K) & 1) continue;
        int q = p | (1 << K);
        ull send = b ? A[p] : A[q];
        ull recv = __shfl_xor_sync(0xffffffffu, send, mask);
        if (b) A[p] = recv; else A[q] = recv;
    }
}

__device__ __forceinline__ void iter_p(ull* R, ull* I, const ull* G) {
    {
        ull c = G[62], s = G[63], ns = G[64];
#pragma unroll
        for (int p = 2; p < 8; p += 4) {
            int q = p + 1;
            ull ar = R[p], ai = I[p], br = R[q], bi = I[q];
            R[p] = fma2(c, ar, mul2(s,  bi)); I[p] = fma2(c, ai, mul2(ns, br));
            R[q] = fma2(c, br, mul2(s,  ai)); I[q] = fma2(c, bi, mul2(ns, ar));
        }
    }
    {
        ull c = G[65], s = G[66], ns = G[67];
#pragma unroll
        for (int p = 4; p < 8; p += 2) {
            int q = p + 1;
            ull ar = R[p], ai = I[p], br = R[q], bi = I[q];
            R[p] = fma2(c, ar, mul2(ns, br)); I[p] = fma2(c, ai, mul2(ns, bi));
            R[q] = fma2(c, br, mul2(s,  ar)); I[q] = fma2(c, bi, mul2(s,  ai));
        }
    }
    {
        ull c = G[68], sp = G[69], sn = G[70];
#pragma unroll
        for (int pp = 0; pp < 4; pp++) {
            int p = (pp < 2) ? 2 + pp : 4 + pp;
            ull t = R[p];
            R[p] = fma2(c, t, mul2(sp, I[p]));
            I[p] = fma2(c, I[p], mul2(sn, t));
        }
    }
    {
        ull c = G[71], sm = G[72];
#pragma unroll
        for (int p = 4; p < 8; p++) {
            ull RS = hsw(R[p]), IS = hsw(I[p]);
            R[p] = fma2(c, R[p], mul2(sm, RS));
            I[p] = fma2(c, I[p], mul2(sm, IS));
        }
    }
    ap_p<2, false>(R, I, G + 0);
    ap_p<1, false>(R, I, G + 8);
    ap_p<0, false>(R, I, G + 16);
    swp(R[4], R[6]); swp(R[5], R[7]); swp(I[4], I[6]); swp(I[5], I[7]);
    swp(R[2], R[3]); swp(R[6], R[7]); swp(I[2], I[3]); swp(I[6], I[7]);
    swp(R[1], R[5]); swp(R[3], R[7]); swp(I[1], I[5]); swp(I[3], I[7]);
    ap_p<0, false>(R, I, G + 24);
    ap_p<1, false>(R, I, G + 32);
    {
        ull A = G[56], B = G[57], Gm = G[58], D = G[59], Ap = G[60], Bp = G[61];
#pragma unroll
        for (int p = 0; p < 8; p++) {
            ull RS = hsw(R[p]), IS = hsw(I[p]);
            ull nr = fma2(A,  R[p], fma2(B,  RS, fma2(Gm, I[p], mul2(D, IS))));
            ull ni = fma2(Ap, R[p], fma2(Bp, RS, fma2(A,  I[p], mul2(B, IS))));
            R[p] = nr; I[p] = ni;
        }
    }
    swp(R[1], R[3]); swp(R[5], R[7]); swp(I[1], I[3]); swp(I[5], I[7]);
    R[2] = hsw(R[2]); R[3] = hsw(R[3]); R[6] = hsw(R[6]); R[7] = hsw(R[7]);
    I[2] = hsw(I[2]); I[3] = hsw(I[3]); I[6] = hsw(I[6]); I[7] = hsw(I[7]);
#pragma unroll
    for (int p = 0; p < 8; p += 2) { yswp(R[p], R[p + 1]); yswp(I[p], I[p + 1]); }
}

// ---------------- gate precompute ----------------
__device__ void make_rot(const float* w, float2* m) {
    float phi = w[0], th = w[1], om = w[2];
    float c, s; sincosf(th * 0.5f, &s, &c);
    float sa, ca, sb, cb;
    sincosf((phi + om) * 0.5f, &sa, &ca);
    sincosf((phi - om) * 0.5f, &sb, &cb);
    m[0] = make_float2(c * ca, -c * sa);
    m[1] = make_float2(-s * cb, -s * sb);
    m[2] = make_float2(s * cb, -s * sb);
    m[3] = make_float2(c * ca, c * sa);
}
__device__ void cm2(const float2* A, const float2* B, float2* C) {
    C[0] = cadd(cmul(A[0], B[0]), cmul(A[1], B[2]));
    C[1] = cadd(cmul(A[0], B[1]), cmul(A[1], B[3]));
    C[2] = cadd(cmul(A[2], B[0]), cmul(A[3], B[2]));
    C[3] = cadd(cmul(A[2], B[1]), cmul(A[3], B[3]));
}
__device__ void prep_gates(const float* strong, const float* inits, const float* update) {
    float c, s;
    sincosf(inits[0] * 0.5f, &s, &c); g_gates[0] = make_float2(c, s);
    sincosf(inits[1] * 0.5f, &s, &c); g_gates[1] = make_float2(c, s);
    sincosf(inits[2] * 0.5f, &s, &c); g_gates[2] = make_float2(c, s);
    sincosf(inits[3] * 0.5f, &s, &c); g_gates[3] = make_float2(c, s);
    float2 M[4], Q[4];
    make_rot(strong + 0,  M); for (int k = 0; k < 4; k++) g_gates[4 + k]  = M[k];
    make_rot(strong + 3,  M); for (int k = 0; k < 4; k++) g_gates[8 + k]  = M[k];
    make_rot(strong + 6,  M); for (int k = 0; k < 4; k++) g_gates[12 + k] = M[k];
    make_rot(strong + 9,  M); for (int k = 0; k < 4; k++) g_gates[16 + k] = M[k];
    make_rot(strong + 12, M); for (int k = 0; k < 4; k++) g_gates[20 + k] = M[k];
    make_rot(strong + 15, M); for (int k = 0; k < 4; k++) g_gates[24 + k] = M[k];
    const float rh = 0.70710678118654752f;
    float2 H2[4];
    H2[0] = make_float2(rh, 0); H2[1] = make_float2(rh, 0);
    H2[2] = make_float2(rh, 0); H2[3] = make_float2(-rh, 0);
    make_rot(update + 0, M); cm2(H2, M, Q); for (int k = 0; k < 4; k++) g_gates[28 + k] = Q[k];
    make_rot(update + 3, M); cm2(H2, M, Q); for (int k = 0; k < 4; k++) g_gates[32 + k] = Q[k];
}
__device__ void pack8(const float2* m, ull* d) {
    d[0] = pk(m[0].x, m[0].x); d[1] = pk(m[0].y, m[0].y); d[2] = pk(-m[0].y, -m[0].y);
    d[3] = pk(m[1].x, m[1].x); d[4] = pk(-m[1].x, -m[1].x); d[5] = pk(m[1].y, m[1].y);
    d[6] = pk(-m[1].y, -m[1].y); d[7] = pk(-m[0].x, -m[0].x);
}
__device__ void pack_all() {
    pack8(&g_gates[4],  &g_gp[0]);
    pack8(&g_gates[8],  &g_gp[8]);
    pack8(&g_gates[12], &g_gp[16]);
    pack8(&g_gates[16], &g_gp[24]);
    pack8(&g_gates[20], &g_gp[32]);
    pack8(&g_gates[28], &g_gp[40]);
    pack8(&g_gates[32], &g_gp[48]);
    float2 m0 = g_gates[24], m1 = g_gates[25], m2 = g_gates[26], m3 = g_gates[27];
    g_gp[56] = pk(m0.x, m3.x);  g_gp[57] = pk(m1.x, m2.x);
    g_gp[58] = pk(-m0.y, -m3.y); g_gp[59] = pk(-m1.y, -m2.y);
    g_gp[60] = pk(m0.y, m3.y);  g_gp[61] = pk(m1.y, m2.y);
    float c, s;
    c = g_gates[0].x; s = g_gates[0].y;
    g_gp[62] = pk(c, c); g_gp[63] = pk(s, s); g_gp[64] = pk(-s, -s);
    c = g_gates[1].x; s = g_gates[1].y;
    g_gp[65] = pk(c, c); g_gp[66] = pk(s, s); g_gp[67] = pk(-s, -s);
    c = g_gates[2].x; s = g_gates[2].y;
    g_gp[68] = pk(c, c); g_gp[69] = pk(s, -s); g_gp[70] = pk(-s, s);
    c = g_gates[3].x; s = g_gates[3].y;
    g_gp[71] = pk(c, c); g_gp[72] = pk(-s, s);
}

// ---------------- K1: node/edge MLP, 8 threads per row (+ prep + packed tables) ----------------
template <int NI, bool IS_NODE>
__device__ __forceinline__ void mlp_phase(const float* __restrict__ inp, int row, int k8,
                                          const float* sMW1, const float* sMb1,
                                          const float* sMW2, const float* sMb2) {
    float in[NI];
#pragma unroll
    for (int i = 0; i < NI; i++) in[i] = inp[row * NI + i];
    float o0 = 0.f, o1 = 0.f;
#pragma unroll
    for (int j = 0; j < 16; j++) {
        int h = k8 + 8 * j;
        float a = sMb1[h];
#pragma unroll
        for (int i = 0; i < NI; i++) a = fmaf(in[i], sMW1[i * 128 + h], a);
        a = a > 0.f ? a : 0.01f * a;
        o0 = fmaf(a, sMW2[2 * h], o0);
        o1 = fmaf(a, sMW2[2 * h + 1], o1);
    }
#pragma unroll
    for (int o = 1; o < 8; o <<= 1) {
        o0 += __shfl_xor_sync(0xffffffffu, o0, o);
        o1 += __shfl_xor_sync(0xffffffffu, o1, o);
    }
    if (k8 == 0) {
        o0 += sMb2[0]; o1 += sMb2[1];
        float t0 = tanhf(o0) * PI_F;
        float t1 = tanhf(o1) * PI_F;
        float sy, cy, sz, cz;
        sincosf(0.5f * t0, &sy, &cy);
        sincosf(0.5f * t1, &sz, &cz);
        float4 amps = make_float4(cy * cz, -cy * sz, sy * cz, sy * sz);
        if (IS_NODE) {
            g_x[2 * row] = t0; g_x[2 * row + 1] = t1;
            g_x4[row] = amps;
        } else {
            g_e4[row] = amps;
        }
    }
}

__global__ void __launch_bounds__(128) mlp_fused_kernel(
    const float* __restrict__ node_feat,
    const float* __restrict__ Wn1, const float* __restrict__ bn1,
    const float* __restrict__ Wn2, const float* __restrict__ bn2,
    const float* __restrict__ edge_attr,
    const float* __restrict__ We1, const float* __restrict__ be1,
    const float* __restrict__ We2, const float* __restrict__ be2,
    const float* __restrict__ strong, const float* __restrict__ inits,
    const float* __restrict__ update) {
    __shared__ float sW1[8 * 128];
    __shared__ float sb1[128];
    __shared__ float sW2[256];
    __shared__ float sb2[2];
    int b = blockIdx.x, tid = threadIdx.x;
    bool isNode = (b < 256);
    const float* W1 = isNode ? Wn1 : We1;
    const float* b1 = isNode ? bn1 : be1;
    const float* W2 = isNode ? Wn2 : We2;
    const float* b2 = isNode ? bn2 : be2;
    int ni = isNode ? 8 : 4;
    for (int k = tid; k < ni * 128; k += 128) sW1[k] = W1[k];
    sb1[tid] = b1[tid];
    sW2[tid] = W2[tid]; sW2[128 + tid] = W2[128 + tid];
    if (tid < 2) sb2[tid] = b2[tid];

    if (b == 0) {
        if (tid < NUM_GRAPHS) {
            g_gsum[2 * tid] = 0.f; g_gsum[2 * tid + 1] = 0.f; g_gcnt[tid] = 0.f;
        }
        if (tid == 33) g_done = 0;
        if (tid == 32) prep_gates(strong, inits, update);
    }
    __syncthreads();

    if (b == 0) {
        if (tid == 48) pack_all();
        if (tid >= 64 && tid < 68) {
            int k = tid - 64;
            float2 v[16];
#pragma unroll
            for (int r = 0; r < 16; r++) v[r] = make_float2(0.f, 0.f);
            v[((k >> 1) << 3) | ((k & 1) << 2)] = make_float2(1.f, 0.f);
            iter_regs_s(v, g_gates);
#pragma unroll
            for (int p = 0; p < 8; p++) {
                g_wp[k * 16 + p]     = pk(v[2 * p].x, v[2 * p + 1].x);
                g_wp[k * 16 + 8 + p] = pk(v[2 * p].y, v[2 * p + 1].y);
            }
        }
    }

    int k8 = tid & 7;
    int rowLocal = tid >> 3;
    if (isNode)
        mlp_phase<8, true>(node_feat, b * 16 + rowLocal, k8, sW1, sb1, sW2, sb2);
    else
        mlp_phase<4, false>(edge_attr, (b - 256) * 16 + rowLocal, k8, sW1, sb1, sW2, sb2);
}

// ================= PQC kernel (packed f32x2, PDL secondary) =================
__device__ __forceinline__ float2 pick(float4 a, int bit) {
    return bit ? make_float2(a.z, a.w) : make_float2(a.x, a.y);
}

__global__ void __launch_bounds__(128, 6) pqc_kernel(
    const int* __restrict__ subgraphs, const int* __restrict__ edge_ids,
    const int* __restrict__ batch,
    const float* __restrict__ Wu1, const float* __restrict__ bu1,
    const float* __restrict__ Wu2, const float* __restrict__ bu2,
    const float* __restrict__ Wh1, const float* __restrict__ bh1,
    const float* __restrict__ Wh2, const float* __restrict__ bh2,
    float* __restrict__ out) {
    __shared__ ull sGP[73];
    __shared__ ull sWP[64];
    __shared__ float sW1[384];
    __shared__ float sb1[128];
    __shared__ float sW2[256];
    __shared__ float sb2[2];
    __shared__ float sAcc[NUM_GRAPHS * 3];
    __shared__ int sLast;
    int tid = threadIdx.x;

    // ---- prologue: harness-input-only loads (run while mlp kernel drains) ----
    for (int k = tid; k < 384; k += 128) sW1[k] = Wu1[k];
    sb1[tid] = bu1[tid];
    sW2[tid] = Wu2[tid]; sW2[128 + tid] = Wu2[128 + tid];
    if (tid < 2) sb2[tid] = bu2[tid];
    if (tid < NUM_GRAPHS * 3) sAcc[tid] = 0.f;

    int lane = tid & 31;
    int s = blockIdx.x * 4 + (tid >> 5);
    int e0 = edge_ids[3 * s], e1 = edge_ids[3 * s + 1], e2 = edge_ids[3 * s + 2];
    int n0 = subgraphs[4 * s], n1 = subgraphs[4 * s + 1],
        n2 = subgraphs[4 * s + 2], n3 = subgraphs[4 * s + 3];

    // ---- wait for mlp kernel results, then touch mlp-produced state ----
    cudaGridDependencySynchronize();

    for (int k = tid; k < 73; k += 128) sGP[k] = g_gp[k];
    for (int k = tid; k < 64; k += 128) sWP[k] = g_wp[k];
    __syncthreads();

    float x0c = g_x[2 * n0], x1c = g_x[2 * n0 + 1];

    float2 lf = pick(g_e4[e1], (lane >> 4) & 1);
    lf = cmul(lf, pick(g_e4[e2], (lane >> 3) & 1));
    lf = cmul(lf, pick(g_x4[n0], (lane >> 2) & 1));
    lf = cmul(lf, pick(g_x4[n2], (lane >> 1) & 1));
    lf = cmul(lf, pick(g_x4[n3], lane & 1));
    float4 aw0 = g_e4[e0];
    float4 aw4 = g_x4[n1];

    float2 c0 = cmul(lf, cmul(pick(aw0, 0), pick(aw4, 0)));
    float2 c1 = cmul(lf, cmul(pick(aw0, 0), pick(aw4, 1)));
    float2 c2 = cmul(lf, cmul(pick(aw0, 1), pick(aw4, 0)));
    float2 c3 = cmul(lf, cmul(pick(aw0, 1), pick(aw4, 1)));

    ull R[8], I[8];
    {
        ull c0x = pk(c0.x, c0.x), c0y = pk(c0.y, c0.y), m0 = pk(-c0.y, -c0.y);
        ull c1x = pk(c1.x, c1.x), c1y = pk(c1.y, c1.y), m1 = pk(-c1.y, -c1.y);
        ull c2x = pk(c2.x, c2.x), c2y = pk(c2.y, c2.y), m2 = pk(-c2.y, -c2.y);
        ull c3x = pk(c3.x, c3.x), c3y = pk(c3.y, c3.y), m3 = pk(-c3.y, -c3.y);
#pragma unroll
        for (int p = 0; p < 8; p++) {
            ull w0r = sWP[p],      w0i = sWP[8 + p];
            ull w1r = sWP[16 + p], w1i = sWP[24 + p];
            ull w2r = sWP[32 + p], w2i = sWP[40 + p];
            ull w3r = sWP[48 + p], w3i = sWP[56 + p];
            R[p] = fma2(c0x, w0r, fma2(m0, w0i,
                   fma2(c1x, w1r, fma2(m1, w1i,
                   fma2(c2x, w2r, fma2(m2, w2i,
                   fma2(c3x, w3r, mul2(m3, w3i))))))));
            I[p] = fma2(c0y, w0r, fma2(c0x, w0i,
                   fma2(c1y, w1r, fma2(c1x, w1i,
                   fma2(c2y, w2r, fma2(c2x, w2i,
                   fma2(c3y, w3r, mul2(c3x, w3i))))))));
        }
    }

    swap_p<2>(R, lane, 16); swap_p<2>(I, lane, 16);
    swap_p<1>(R, lane, 2);  swap_p<1>(I, lane, 2);
    iter_p(R, I, sGP);
    swap_p<2>(R, lane, 8);  swap_p<2>(I, lane, 8);
    swap_p<1>(R, lane, 1);  swap_p<1>(I, lane, 1);
    iter_p(R, I, sGP);
    swap_p<2>(R, lane, 4);  swap_p<2>(I, lane, 4);

    ap_p<2, true>(R, I, sGP + 40);
    ap_p<0, true>(R, I, sGP + 48);

    float part = 0.f;
#pragma unroll
    for (int p = 0; p < 8; p++) {
        ull t = fma2(R[p], R[p], mul2(I[p], I[p]));
        float x, y; upk(t, x, y);
        float v2 = x + y;
        part = (((p >> 2) ^ p) & 1) ? part - v2 : part + v2;
    }
#pragma unroll
    for (int o = 16; o; o >>= 1) part += __shfl_xor_sync(0xffffffffu, part, o);
    float aggr = part;

    float o0 = 0.f, o1 = 0.f;
#pragma unroll
    for (int k = 0; k < 4; k++) {
        int h = lane + 32 * k;
        float a = fmaf(x0c, sW1[h],
                  fmaf(x1c, sW1[128 + h],
                  fmaf(aggr, sW1[256 + h], sb1[h])));
        a = a > 0.f ? a : 0.01f * a;
        o0 = fmaf(a, sW2[2 * h], o0);
        o1 = fmaf(a, sW2[2 * h + 1], o1);
    }
#pragma unroll
    for (int o = 16; o; o >>= 1) {
        o0 += __shfl_xor_sync(0xffffffffu, o0, o);
        o1 += __shfl_xor_sync(0xffffffffu, o1, o);
    }
    if (lane == 0) {
        o0 += sb2[0]; o1 += sb2[1];
        int gu = batch[n0];
        int gx = batch[s];
        atomicAdd(&sAcc[3 * gu + 0], o0);
        atomicAdd(&sAcc[3 * gu + 1], o1);
        atomicAdd(&sAcc[3 * gx + 0], g_x[2 * s]);
        atomicAdd(&sAcc[3 * gx + 1], g_x[2 * s + 1]);
        atomicAdd(&sAcc[3 * gx + 2], 1.f);
    }
    __syncthreads();

    if (tid < NUM_GRAPHS) {
        atomicAdd(&g_gsum[2 * tid],     sAcc[3 * tid + 0]);
        atomicAdd(&g_gsum[2 * tid + 1], sAcc[3 * tid + 1]);
        atomicAdd(&g_gcnt[tid],         sAcc[3 * tid + 2]);
        __threadfence();
    }
    __syncthreads();
    if (tid == 0) {
        int old = atomicAdd(&g_done, 1);
        sLast = (old == PQC_BLOCKS - 1);
        __threadfence();
    }
    __syncthreads();

    if (sLast && tid < NUM_GRAPHS) {
        int g = tid;
        float cnt = __ldcg(&g_gcnt[g]);
        float g0 = __ldcg(&g_gsum[2 * g]) / cnt;
        float g1 = __ldcg(&g_gsum[2 * g + 1]) / cnt;
        float h0 = g0 * Wh1[0] + g1 * Wh1[2] + bh1[0];
        float h1 = g0 * Wh1[1] + g1 * Wh1[3] + bh1[1];
        h0 = h0 > 0.f ? h0 : 0.01f * h0;
        h1 = h1 > 0.f ? h1 : 0.01f * h1;
        out[2 * g]     = h0 * Wh2[0] + h1 * Wh2[2] + bh2[0];
        out[2 * g + 1] = h0 * Wh2[1] + h1 * Wh2[3] + bh2[1];
    }
}

// ---------------- launch ----------------
extern "C" void kernel_launch(void* const* d_in, const int* in_sizes, int n_in,
                              void* d_out, int out_size) {
    const float* node_feat = (const float*)d_in[0];
    const float* edge_attr = (const float*)d_in[1];
    const float* Wn1 = (const float*)d_in[2];
    const float* bn1 = (const float*)d_in[3];
    const float* Wn2 = (const float*)d_in[4];
    const float* bn2 = (const float*)d_in[5];
    const float* We1 = (const float*)d_in[6];
    const float* be1 = (const float*)d_in[7];
    const float* We2 = (const float*)d_in[8];
    const float* be2 = (const float*)d_in[9];
    const float* strong = (const float*)d_in[10];
    const float* inits  = (const float*)d_in[11];
    const float* update = (const float*)d_in[12];
    const float* Wu1 = (const float*)d_in[13];
    const float* bu1 = (const float*)d_in[14];
    const float* Wu2 = (const float*)d_in[15];
    const float* bu2 = (const float*)d_in[16];
    const float* Wh1 = (const float*)d_in[17];
    const float* bh1 = (const float*)d_in[18];
    const float* Wh2 = (const float*)d_in[19];
    const float* bh2 = (const float*)d_in[20];
    const int* subgraphs = (const int*)d_in[21];
    const int* edge_ids  = (const int*)d_in[22];
    const int* batch     = (const int*)d_in[23];
    float* out = (float*)d_out;

    mlp_fused_kernel<<<1024, 128>>>(node_feat, Wn1, bn1, Wn2, bn2,
                                    edge_attr, We1, be1, We2, be2,
                                    strong, inits, update);

    // PDL: pqc blocks launch while mlp drains; cudaGridDependencySynchronize()
    // inside pqc orders all reads of mlp-produced state.
    cudaLaunchConfig_t cfg = {};
    cfg.gridDim = dim3(PQC_BLOCKS);
    cfg.blockDim = dim3(128);
    cfg.dynamicSmemBytes = 0;
    cudaLaunchAttribute attrs[1];
    attrs[0].id = cudaLaunchAttributeProgrammaticStreamSerialization;
    attrs[0].val.programmaticStreamSerializationAllowed = 1;
    cfg.attrs = attrs;
    cfg.numAttrs = 1;
    cudaLaunchKernelEx(&cfg, pqc_kernel,
                       subgraphs, edge_ids, batch,
                       Wu1, bu1, Wu2, bu2,
                       Wh1, bh1, Wh2, bh2, out);
}